// round 2
// baseline (speedup 1.0000x reference)
#include <cuda_runtime.h>
#include <math.h>

#define S_LEN   2048
#define BATCH   2
#define DMODEL  1024
#define NHEAD   16
#define NKV     4
#define HEADDIM 64
#define NTOK    4096            // S_LEN * BATCH
#define DFF     4096            // 4 * DMODEL
#define QKVN    1536            // 1024 + 256 + 256
#define EPS_F   1e-5f
#define QK_SCALE 0.03125f       // D^-0.5 = 1/32

// ---------------- scratch (__device__ globals; no allocation allowed) ----------------
__device__ float g_h   [NTOK * DMODEL];
__device__ float g_wqkv[DMODEL * QKVN];
__device__ float g_bqkv[QKVN];
__device__ float g_qkv [NTOK * QKVN];
__device__ float g_q   [BATCH * NHEAD * S_LEN * HEADDIM];
__device__ float g_k   [BATCH * NKV   * S_LEN * HEADDIM];
__device__ float g_v   [BATCH * NKV   * S_LEN * HEADDIM];
__device__ float g_attn[NTOK * DMODEL];
__device__ float g_x1  [NTOK * DMODEL];
__device__ float g_h2  [NTOK * DMODEL];
__device__ float g_mid [NTOK * DFF];

// ---------------- pack wq|wk|wv into one [D, 1536] weight ----------------
__global__ void pack_wqkv_kernel(const float* __restrict__ wq, const float* __restrict__ wk,
                                 const float* __restrict__ wv, const float* __restrict__ bq,
                                 const float* __restrict__ bk, const float* __restrict__ bv,
                                 float* __restrict__ W, float* __restrict__ bias)
{
    int idx = blockIdx.x * 256 + threadIdx.x;
    if (idx < DMODEL * QKVN) {
        int k = idx / QKVN, c = idx % QKVN;
        float v;
        if (c < 1024)       v = wq[k * 1024 + c];
        else if (c < 1280)  v = wk[k * 256 + (c - 1024)];
        else                v = wv[k * 256 + (c - 1280)];
        W[idx] = v;
    }
    if (idx < QKVN) {
        bias[idx] = (idx < 1024) ? bq[idx] : (idx < 1280 ? bk[idx - 1024] : bv[idx - 1280]);
    }
}

// ---------------- RMSNorm over D=1024, one block per row ----------------
__global__ __launch_bounds__(256)
void rmsnorm_kernel(const float* __restrict__ x, const float* __restrict__ w,
                    float* __restrict__ y)
{
    int row = blockIdx.x;
    int i = threadIdx.x;
    const float* xr = x + (size_t)row * DMODEL;
    float4 xv = *(const float4*)(xr + i * 4);
    float ss = xv.x * xv.x + xv.y * xv.y + xv.z * xv.z + xv.w * xv.w;
    #pragma unroll
    for (int off = 16; off; off >>= 1) ss += __shfl_xor_sync(0xffffffffu, ss, off);
    __shared__ float red[8];
    __shared__ float s_sc;
    if ((i & 31) == 0) red[i >> 5] = ss;
    __syncthreads();
    if (i == 0) {
        float tot = 0.f;
        #pragma unroll
        for (int kk = 0; kk < 8; kk++) tot += red[kk];
        s_sc = rsqrtf(tot * (1.0f / DMODEL) + EPS_F);
    }
    __syncthreads();
    float sc = s_sc;
    float4 wv = *(const float4*)(w + i * 4);
    float4 ov = make_float4(xv.x * sc * wv.x, xv.y * sc * wv.y,
                            xv.z * sc * wv.z, xv.w * sc * wv.w);
    *(float4*)(y + (size_t)row * DMODEL + i * 4) = ov;
}

// ---------------- per-head QK RMSNorm + RoPE + relayout; V relayout ----------------
// grid: (NTOK, 24) blockDim 64. slots 0..15 = q heads, 16..19 = k heads, 20..23 = v heads
__global__ __launch_bounds__(64)
void qkrope_kernel(const float* __restrict__ qkv, const float* __restrict__ qn_w,
                   const float* __restrict__ kn_w, float* __restrict__ Qo,
                   float* __restrict__ Ko, float* __restrict__ Vo)
{
    int t = blockIdx.x;            // token = s*BATCH + b
    int slot = blockIdx.y;
    int i = threadIdx.x;           // 0..63
    int s = t / BATCH, b = t % BATCH;
    __shared__ float buf[64];
    __shared__ float red[2];

    if (slot >= 20) {   // V: pure relayout
        int vh = slot - 20;
        float v = qkv[(size_t)t * QKVN + 1280 + vh * 64 + i];
        Vo[((size_t)(b * NKV + vh) * S_LEN + s) * 64 + i] = v;
        return;
    }

    bool is_q = (slot < 16);
    int col = is_q ? (slot * 64 + i) : (1024 + (slot - 16) * 64 + i);
    float v = qkv[(size_t)t * QKVN + col];
    float ss = v * v;
    #pragma unroll
    for (int off = 16; off; off >>= 1) ss += __shfl_xor_sync(0xffffffffu, ss, off);
    if ((i & 31) == 0) red[i >> 5] = ss;
    __syncthreads();
    float tot = red[0] + red[1];
    float sc = rsqrtf(tot * (1.0f / 64.0f) + EPS_F);
    const float* w = is_q ? qn_w : kn_w;
    float nv = v * sc * w[i];
    buf[i] = nv;
    __syncthreads();
    float rot = (i < 32) ? -buf[i + 32] : buf[i - 32];
    int j = i & 31;
    // inv_freq = 10000^(-j/32) = 2^(-j/32 * log2(10000))
    float invf = exp2f(-(float)j * (13.287712379549449f / 32.0f));
    float ang = (float)s * invf;
    float sn, cs;
    sincosf(ang, &sn, &cs);
    float outv = nv * cs + rot * sn;
    if (is_q) {
        outv *= QK_SCALE;  // fold score scale into q
        Qo[((size_t)(b * NHEAD + slot) * S_LEN + s) * 64 + i] = outv;
    } else {
        Ko[((size_t)(b * NKV + (slot - 16)) * S_LEN + s) * 64 + i] = outv;
    }
}

// ---------------- fp32 SIMT GEMM: C[M,N] = A[M,K] @ B[K,N] + bias (+ epilogue) ----------------
// EPI: 0 = +bias, 1 = gelu(+bias), 2 = +bias + residual
// M,N multiples of 128; K multiple of 8.
template<int EPI>
__global__ __launch_bounds__(256)
void gemm_kernel(const float* __restrict__ A, const float* __restrict__ B,
                 const float* __restrict__ bias, const float* __restrict__ res,
                 float* __restrict__ C, int M, int N, int K)
{
    const int BK = 8;
    __shared__ float As[8][128];
    __shared__ float Bs[8][128];
    int tid = threadIdx.x;
    int row0 = blockIdx.y * 128;
    int col0 = blockIdx.x * 128;
    int aRow = tid >> 1;
    int aCol = (tid & 1) << 2;
    int bRow = tid >> 5;
    int bCol = (tid & 31) << 2;
    int tr = tid >> 4, tc = tid & 15;

    const float* Ap = A + (size_t)(row0 + aRow) * K + aCol;
    const float* Bp = B + (size_t)bRow * N + col0 + bCol;

    float acc[8][8];
    #pragma unroll
    for (int i = 0; i < 8; i++)
        #pragma unroll
        for (int j = 0; j < 8; j++) acc[i][j] = 0.f;

    for (int k0 = 0; k0 < K; k0 += BK) {
        float4 av = *(const float4*)Ap;
        float4 bv = *(const float4*)Bp;
        Ap += BK;
        Bp += (size_t)BK * N;
        As[aCol + 0][aRow] = av.x; As[aCol + 1][aRow] = av.y;
        As[aCol + 2][aRow] = av.z; As[aCol + 3][aRow] = av.w;
        *(float4*)&Bs[bRow][bCol] = bv;
        __syncthreads();
        #pragma unroll
        for (int k = 0; k < 8; k++) {
            float4 a0 = *(const float4*)&As[k][tr * 8];
            float4 a1 = *(const float4*)&As[k][tr * 8 + 4];
            float4 b0 = *(const float4*)&Bs[k][tc * 8];
            float4 b1 = *(const float4*)&Bs[k][tc * 8 + 4];
            float a[8] = {a0.x, a0.y, a0.z, a0.w, a1.x, a1.y, a1.z, a1.w};
            float b[8] = {b0.x, b0.y, b0.z, b0.w, b1.x, b1.y, b1.z, b1.w};
            #pragma unroll
            for (int i = 0; i < 8; i++)
                #pragma unroll
                for (int j = 0; j < 8; j++)
                    acc[i][j] += a[i] * b[j];
        }
        __syncthreads();
    }

    int crow = row0 + tr * 8;
    int ccol = col0 + tc * 8;
    float bvals[8];
    #pragma unroll
    for (int j = 0; j < 8; j++) bvals[j] = bias[ccol + j];
    #pragma unroll
    for (int i = 0; i < 8; i++) {
        float* Cp = C + (size_t)(crow + i) * N + ccol;
        float out[8];
        #pragma unroll
        for (int j = 0; j < 8; j++) {
            float v = acc[i][j] + bvals[j];
            if (EPI == 1) v = 0.5f * v * (1.0f + erff(v * 0.70710678118654752f));
            out[j] = v;
        }
        if (EPI == 2) {
            const float* Rp = res + (size_t)(crow + i) * N + ccol;
            float4 r0 = *(const float4*)&Rp[0];
            float4 r1 = *(const float4*)&Rp[4];
            out[0] += r0.x; out[1] += r0.y; out[2] += r0.z; out[3] += r0.w;
            out[4] += r1.x; out[5] += r1.y; out[6] += r1.z; out[7] += r1.w;
        }
        *(float4*)&Cp[0] = make_float4(out[0], out[1], out[2], out[3]);
        *(float4*)&Cp[4] = make_float4(out[4], out[5], out[6], out[7]);
    }
}

// ---------------- flash attention: BQ=64, BKV=32, causal, GQA ----------------
// grid: (32 q-tiles, BATCH*NHEAD), 256 threads. Q pre-scaled by QK_SCALE.
__global__ __launch_bounds__(256)
void attn_kernel(const float* __restrict__ Q, const float* __restrict__ K,
                 const float* __restrict__ V, float* __restrict__ O)
{
    __shared__ float Qs[64][65];
    __shared__ float Ks[32][65];
    __shared__ float Vs[32][68];
    __shared__ float Ps[64][34];

    int tid = threadIdx.x;
    int qt = blockIdx.x;
    int bh = blockIdx.y;
    int b = bh >> 4;
    int h = bh & 15;
    int kvh = h >> 2;
    const float* Qb = Q + (size_t)(b * NHEAD + h)  * S_LEN * 64;
    const float* Kb = K + (size_t)(b * NKV  + kvh) * S_LEN * 64;
    const float* Vb = V + (size_t)(b * NKV  + kvh) * S_LEN * 64;
    int q0 = qt * 64;

    for (int i = tid; i < 64 * 16; i += 256) {
        int r = i >> 4, c = (i & 15) << 2;
        float4 v = *(const float4*)(Qb + (size_t)(q0 + r) * 64 + c);
        Qs[r][c] = v.x; Qs[r][c + 1] = v.y; Qs[r][c + 2] = v.z; Qs[r][c + 3] = v.w;
    }

    int tr = tid >> 4, tc = tid & 15;
    float m_run[4], l_run[4], o[4][4];
    #pragma unroll
    for (int i = 0; i < 4; i++) {
        m_run[i] = -INFINITY; l_run[i] = 0.f;
        #pragma unroll
        for (int j = 0; j < 4; j++) o[i][j] = 0.f;
    }

    int nkt = 2 * qt + 2;   // kv tiles covering [0, q0+64)
    for (int jt = 0; jt < nkt; ++jt) {
        int j0 = jt * 32;
        __syncthreads();
        for (int i = tid; i < 32 * 16; i += 256) {
            int r = i >> 4, c = (i & 15) << 2;
            float4 kv = *(const float4*)(Kb + (size_t)(j0 + r) * 64 + c);
            Ks[r][c] = kv.x; Ks[r][c + 1] = kv.y; Ks[r][c + 2] = kv.z; Ks[r][c + 3] = kv.w;
            float4 vv = *(const float4*)(Vb + (size_t)(j0 + r) * 64 + c);
            Vs[r][c] = vv.x; Vs[r][c + 1] = vv.y; Vs[r][c + 2] = vv.z; Vs[r][c + 3] = vv.w;
        }
        __syncthreads();

        float s[4][2];
        #pragma unroll
        for (int i = 0; i < 4; i++) { s[i][0] = 0.f; s[i][1] = 0.f; }
        #pragma unroll 16
        for (int k = 0; k < 64; k++) {
            float a0 = Qs[tr * 4 + 0][k], a1 = Qs[tr * 4 + 1][k];
            float a2 = Qs[tr * 4 + 2][k], a3 = Qs[tr * 4 + 3][k];
            float b0 = Ks[tc * 2 + 0][k], b1 = Ks[tc * 2 + 1][k];
            s[0][0] += a0 * b0; s[0][1] += a0 * b1;
            s[1][0] += a1 * b0; s[1][1] += a1 * b1;
            s[2][0] += a2 * b0; s[2][1] += a2 * b1;
            s[3][0] += a3 * b0; s[3][1] += a3 * b1;
        }
        if (j0 + 31 > q0) {   // only the tiles crossing the diagonal
            #pragma unroll
            for (int i = 0; i < 4; i++)
                #pragma unroll
                for (int j = 0; j < 2; j++)
                    if (j0 + tc * 2 + j > q0 + tr * 4 + i) s[i][j] = -INFINITY;
        }
        float mt[4];
        #pragma unroll
        for (int i = 0; i < 4; i++) mt[i] = fmaxf(s[i][0], s[i][1]);
        #pragma unroll
        for (int off = 1; off < 16; off <<= 1)
            #pragma unroll
            for (int i = 0; i < 4; i++)
                mt[i] = fmaxf(mt[i], __shfl_xor_sync(0xffffffffu, mt[i], off));
        float alpha[4], psum[4];
        #pragma unroll
        for (int i = 0; i < 4; i++) {
            float mn = fmaxf(m_run[i], mt[i]);
            alpha[i] = __expf(m_run[i] - mn);
            m_run[i] = mn;
            float p0 = __expf(s[i][0] - mn);
            float p1 = __expf(s[i][1] - mn);
            s[i][0] = p0; s[i][1] = p1;
            psum[i] = p0 + p1;
        }
        #pragma unroll
        for (int off = 1; off < 16; off <<= 1)
            #pragma unroll
            for (int i = 0; i < 4; i++)
                psum[i] += __shfl_xor_sync(0xffffffffu, psum[i], off);
        #pragma unroll
        for (int i = 0; i < 4; i++) {
            l_run[i] = l_run[i] * alpha[i] + psum[i];
            #pragma unroll
            for (int j = 0; j < 4; j++) o[i][j] *= alpha[i];
            *(float2*)&Ps[tr * 4 + i][tc * 2] = make_float2(s[i][0], s[i][1]);
        }
        __syncthreads();
        #pragma unroll 8
        for (int k = 0; k < 32; k++) {
            float4 vv = *(const float4*)&Vs[k][tc * 4];
            float p0 = Ps[tr * 4 + 0][k], p1 = Ps[tr * 4 + 1][k];
            float p2 = Ps[tr * 4 + 2][k], p3 = Ps[tr * 4 + 3][k];
            o[0][0] += p0 * vv.x; o[0][1] += p0 * vv.y; o[0][2] += p0 * vv.z; o[0][3] += p0 * vv.w;
            o[1][0] += p1 * vv.x; o[1][1] += p1 * vv.y; o[1][2] += p1 * vv.z; o[1][3] += p1 * vv.w;
            o[2][0] += p2 * vv.x; o[2][1] += p2 * vv.y; o[2][2] += p2 * vv.z; o[2][3] += p2 * vv.w;
            o[3][0] += p3 * vv.x; o[3][1] += p3 * vv.y; o[3][2] += p3 * vv.z; o[3][3] += p3 * vv.w;
        }
    }
    #pragma unroll
    for (int i = 0; i < 4; i++) {
        float inv = 1.0f / l_run[i];
        int srow = q0 + tr * 4 + i;
        float* dst = O + ((size_t)srow * BATCH + b) * DMODEL + h * 64 + tc * 4;
        *(float4*)dst = make_float4(o[i][0] * inv, o[i][1] * inv, o[i][2] * inv, o[i][3] * inv);
    }
}

// ---------------- host orchestration ----------------
extern "C" void kernel_launch(void* const* d_in, const int* in_sizes, int n_in,
                              void* d_out, int out_size)
{
    const float* x   = (const float*)d_in[0];
    const float* n1w = (const float*)d_in[1];
    const float* wq  = (const float*)d_in[2];
    const float* bq  = (const float*)d_in[3];
    const float* wk  = (const float*)d_in[4];
    const float* bk  = (const float*)d_in[5];
    const float* wv  = (const float*)d_in[6];
    const float* bv  = (const float*)d_in[7];
    const float* qnw = (const float*)d_in[8];
    const float* knw = (const float*)d_in[9];
    const float* wo  = (const float*)d_in[10];
    const float* bo  = (const float*)d_in[11];
    const float* n2w = (const float*)d_in[12];
    const float* w1  = (const float*)d_in[13];
    const float* b1  = (const float*)d_in[14];
    const float* w2  = (const float*)d_in[15];
    const float* b2  = (const float*)d_in[16];

    float *ph, *pwqkv, *pbqkv, *pqkv, *pq, *pk, *pv, *pattn, *px1, *ph2, *pmid;
    cudaGetSymbolAddress((void**)&ph,    g_h);
    cudaGetSymbolAddress((void**)&pwqkv, g_wqkv);
    cudaGetSymbolAddress((void**)&pbqkv, g_bqkv);
    cudaGetSymbolAddress((void**)&pqkv,  g_qkv);
    cudaGetSymbolAddress((void**)&pq,    g_q);
    cudaGetSymbolAddress((void**)&pk,    g_k);
    cudaGetSymbolAddress((void**)&pv,    g_v);
    cudaGetSymbolAddress((void**)&pattn, g_attn);
    cudaGetSymbolAddress((void**)&px1,   g_x1);
    cudaGetSymbolAddress((void**)&ph2,   g_h2);
    cudaGetSymbolAddress((void**)&pmid,  g_mid);

    pack_wqkv_kernel<<<(DMODEL * QKVN + 255) / 256, 256>>>(wq, wk, wv, bq, bk, bv, pwqkv, pbqkv);
    rmsnorm_kernel<<<NTOK, 256>>>(x, n1w, ph);
    gemm_kernel<0><<<dim3(QKVN / 128, NTOK / 128), 256>>>(ph, pwqkv, pbqkv, nullptr, pqkv,
                                                          NTOK, QKVN, DMODEL);
    qkrope_kernel<<<dim3(NTOK, 24), 64>>>(pqkv, qnw, knw, pq, pk, pv);
    attn_kernel<<<dim3(S_LEN / 64, BATCH * NHEAD), 256>>>(pq, pk, pv, pattn);
    gemm_kernel<2><<<dim3(DMODEL / 128, NTOK / 128), 256>>>(pattn, wo, bo, x, px1,
                                                            NTOK, DMODEL, DMODEL);
    rmsnorm_kernel<<<NTOK, 256>>>(px1, n2w, ph2);
    gemm_kernel<1><<<dim3(DFF / 128, NTOK / 128), 256>>>(ph2, w1, b1, nullptr, pmid,
                                                         NTOK, DFF, DMODEL);
    gemm_kernel<2><<<dim3(DMODEL / 128, NTOK / 128), 256>>>(pmid, w2, b2, px1, (float*)d_out,
                                                            NTOK, DMODEL, DFF);
}

// round 4
// speedup vs baseline: 2.0094x; 2.0094x over previous
#include <cuda_runtime.h>
#include <math.h>

#define S_LEN   2048
#define BATCH   2
#define DMODEL  1024
#define NHEAD   16
#define NKV     4
#define HEADDIM 64
#define NTOK    4096            // S_LEN * BATCH
#define DFF     4096            // 4 * DMODEL
#define QKVN    1536            // 1024 + 256 + 256
#define EPS_F   1e-5f
#define QK_SCALE 0.03125f       // D^-0.5 = 1/32

// ---------------- scratch (__device__ globals; no allocation allowed) ----------------
__device__ float g_h   [NTOK * DMODEL];
__device__ float g_wqkv[DMODEL * QKVN];
__device__ float g_bqkv[QKVN];
__device__ float g_qkv [NTOK * QKVN];
__device__ float g_q   [BATCH * NHEAD * S_LEN * HEADDIM];
__device__ float g_k   [BATCH * NKV   * S_LEN * HEADDIM];
__device__ float g_v   [BATCH * NKV   * S_LEN * HEADDIM];
__device__ float g_attn[NTOK * DMODEL];
__device__ float g_x1  [NTOK * DMODEL];
__device__ float g_h2  [NTOK * DMODEL];
__device__ float g_mid [NTOK * DFF];

__device__ __forceinline__ unsigned f2tf32(float x) {
    unsigned u;
    asm("cvt.rna.tf32.f32 %0, %1;" : "=r"(u) : "f"(x));
    return u;
}

// ---------------- pack wq|wk|wv into one [D, 1536] weight ----------------
__global__ void pack_wqkv_kernel(const float* __restrict__ wq, const float* __restrict__ wk,
                                 const float* __restrict__ wv, const float* __restrict__ bq,
                                 const float* __restrict__ bk, const float* __restrict__ bv,
                                 float* __restrict__ W, float* __restrict__ bias)
{
    int idx = blockIdx.x * 256 + threadIdx.x;
    if (idx < DMODEL * QKVN) {
        int k = idx / QKVN, c = idx % QKVN;
        float v;
        if (c < 1024)       v = wq[k * 1024 + c];
        else if (c < 1280)  v = wk[k * 256 + (c - 1024)];
        else                v = wv[k * 256 + (c - 1280)];
        W[idx] = v;
    }
    if (idx < QKVN) {
        bias[idx] = (idx < 1024) ? bq[idx] : (idx < 1280 ? bk[idx - 1024] : bv[idx - 1280]);
    }
}

// ---------------- RMSNorm over D=1024, one block per row ----------------
__global__ __launch_bounds__(256)
void rmsnorm_kernel(const float* __restrict__ x, const float* __restrict__ w,
                    float* __restrict__ y)
{
    int row = blockIdx.x;
    int i = threadIdx.x;
    const float* xr = x + (size_t)row * DMODEL;
    float4 xv = *(const float4*)(xr + i * 4);
    float ss = xv.x * xv.x + xv.y * xv.y + xv.z * xv.z + xv.w * xv.w;
    #pragma unroll
    for (int off = 16; off; off >>= 1) ss += __shfl_xor_sync(0xffffffffu, ss, off);
    __shared__ float red[8];
    __shared__ float s_sc;
    if ((i & 31) == 0) red[i >> 5] = ss;
    __syncthreads();
    if (i == 0) {
        float tot = 0.f;
        #pragma unroll
        for (int kk = 0; kk < 8; kk++) tot += red[kk];
        s_sc = rsqrtf(tot * (1.0f / DMODEL) + EPS_F);
    }
    __syncthreads();
    float sc = s_sc;
    float4 wv = *(const float4*)(w + i * 4);
    float4 ov = make_float4(xv.x * sc * wv.x, xv.y * sc * wv.y,
                            xv.z * sc * wv.z, xv.w * sc * wv.w);
    *(float4*)(y + (size_t)row * DMODEL + i * 4) = ov;
}

// ---------------- per-head QK RMSNorm + RoPE + relayout; V relayout ----------------
__global__ __launch_bounds__(64)
void qkrope_kernel(const float* __restrict__ qkv, const float* __restrict__ qn_w,
                   const float* __restrict__ kn_w, float* __restrict__ Qo,
                   float* __restrict__ Ko, float* __restrict__ Vo)
{
    int t = blockIdx.x;            // token = s*BATCH + b
    int slot = blockIdx.y;
    int i = threadIdx.x;           // 0..63
    int s = t / BATCH, b = t % BATCH;
    __shared__ float buf[64];
    __shared__ float red[2];

    if (slot >= 20) {   // V: pure relayout
        int vh = slot - 20;
        float v = qkv[(size_t)t * QKVN + 1280 + vh * 64 + i];
        Vo[((size_t)(b * NKV + vh) * S_LEN + s) * 64 + i] = v;
        return;
    }

    bool is_q = (slot < 16);
    int col = is_q ? (slot * 64 + i) : (1024 + (slot - 16) * 64 + i);
    float v = qkv[(size_t)t * QKVN + col];
    float ss = v * v;
    #pragma unroll
    for (int off = 16; off; off >>= 1) ss += __shfl_xor_sync(0xffffffffu, ss, off);
    if ((i & 31) == 0) red[i >> 5] = ss;
    __syncthreads();
    float tot = red[0] + red[1];
    float sc = rsqrtf(tot * (1.0f / 64.0f) + EPS_F);
    const float* w = is_q ? qn_w : kn_w;
    float nv = v * sc * w[i];
    buf[i] = nv;
    __syncthreads();
    float rot = (i < 32) ? -buf[i + 32] : buf[i - 32];
    int j = i & 31;
    float invf = exp2f(-(float)j * (13.287712379549449f / 32.0f));
    float ang = (float)s * invf;
    float sn, cs;
    sincosf(ang, &sn, &cs);
    float outv = nv * cs + rot * sn;
    if (is_q) {
        outv *= QK_SCALE;
        Qo[((size_t)(b * NHEAD + slot) * S_LEN + s) * 64 + i] = outv;
    } else {
        Ko[((size_t)(b * NKV + (slot - 16)) * S_LEN + s) * 64 + i] = outv;
    }
}

// ---------------- TF32 tensor-core GEMM: C[M,N] = A[M,K] @ B[K,N] + bias (+ epilogue) ----
// EPI: 0 = +bias, 1 = gelu(+bias), 2 = +bias + residual
// Tiles: block 128x128, BK=16, 8 warps of 64x32 (warp grid 2x4).
// mma.sync.m16n8k8 tf32, fp32 accumulate. Double-buffered smem, pad to 136 floats
// so fragment LDS are conflict-free (bank = 8*q + row-lane, all distinct).
template<int EPI>
__global__ __launch_bounds__(256)
void gemm_tf32_kernel(const float* __restrict__ A, const float* __restrict__ B,
                      const float* __restrict__ bias, const float* __restrict__ res,
                      float* __restrict__ C, int M, int N, int K)
{
    __shared__ float As[2][16][136];   // As[k][m]  (A transposed into smem)
    __shared__ float Bs[2][16][136];   // Bs[k][n]

    int tid  = threadIdx.x;
    int wid  = tid >> 5, lane = tid & 31;
    int g    = lane >> 2;              // group 0..7
    int q    = lane & 3;               // 0..3
    int wm   = (wid >> 2) * 64;        // warp m-offset: 0 / 64
    int wn   = (wid & 3) * 32;         // warp n-offset: 0..96

    int row0 = blockIdx.y * 128;
    int col0 = blockIdx.x * 128;

    // global A: each thread 2 float4 along K (rows arow, arow+64)
    int arow = tid >> 2;               // 0..63
    int akc  = (tid & 3) << 2;         // 0,4,8,12
    const float* Ap = A + (size_t)(row0 + arow) * K + akc;
    // global B: each thread 2 float4 along N (k-rows brow, brow+8)
    int brow = tid >> 5;               // 0..7
    int bcol = (tid & 31) << 2;
    const float* Bp = B + (size_t)brow * N + col0 + bcol;

    float acc[4][4][4];
    #pragma unroll
    for (int mt = 0; mt < 4; mt++)
        #pragma unroll
        for (int nt = 0; nt < 4; nt++)
            #pragma unroll
            for (int r = 0; r < 4; r++) acc[mt][nt][r] = 0.f;

    // prologue: stage 0
    {
        float4 a0 = *(const float4*)Ap;
        float4 a1 = *(const float4*)(Ap + (size_t)64 * K);
        float4 b0 = *(const float4*)Bp;
        float4 b1 = *(const float4*)(Bp + (size_t)8 * N);
        As[0][akc + 0][arow] = __uint_as_float(f2tf32(a0.x));
        As[0][akc + 1][arow] = __uint_as_float(f2tf32(a0.y));
        As[0][akc + 2][arow] = __uint_as_float(f2tf32(a0.z));
        As[0][akc + 3][arow] = __uint_as_float(f2tf32(a0.w));
        As[0][akc + 0][arow + 64] = __uint_as_float(f2tf32(a1.x));
        As[0][akc + 1][arow + 64] = __uint_as_float(f2tf32(a1.y));
        As[0][akc + 2][arow + 64] = __uint_as_float(f2tf32(a1.z));
        As[0][akc + 3][arow + 64] = __uint_as_float(f2tf32(a1.w));
        *(float4*)&Bs[0][brow][bcol] = make_float4(
            __uint_as_float(f2tf32(b0.x)), __uint_as_float(f2tf32(b0.y)),
            __uint_as_float(f2tf32(b0.z)), __uint_as_float(f2tf32(b0.w)));
        *(float4*)&Bs[0][brow + 8][bcol] = make_float4(
            __uint_as_float(f2tf32(b1.x)), __uint_as_float(f2tf32(b1.y)),
            __uint_as_float(f2tf32(b1.z)), __uint_as_float(f2tf32(b1.w)));
    }
    __syncthreads();

    int buf = 0;
    for (int k0 = 0; k0 < K; k0 += 16) {
        bool has_next = (k0 + 16) < K;
        float4 a0, a1, b0, b1;
        if (has_next) {
            a0 = *(const float4*)(Ap + k0 + 16);
            a1 = *(const float4*)(Ap + (size_t)64 * K + k0 + 16);
            b0 = *(const float4*)(Bp + (size_t)(k0 + 16) * N);
            b1 = *(const float4*)(Bp + (size_t)(k0 + 24) * N);
        }

        // compute from smem[buf]
        #pragma unroll
        for (int kk = 0; kk < 16; kk += 8) {
            unsigned af[4][4];
            #pragma unroll
            for (int mt = 0; mt < 4; mt++) {
                int r = wm + mt * 16 + g;
                af[mt][0] = __float_as_uint(As[buf][kk + q][r]);
                af[mt][1] = __float_as_uint(As[buf][kk + q][r + 8]);
                af[mt][2] = __float_as_uint(As[buf][kk + 4 + q][r]);
                af[mt][3] = __float_as_uint(As[buf][kk + 4 + q][r + 8]);
            }
            unsigned bf[4][2];
            #pragma unroll
            for (int nt = 0; nt < 4; nt++) {
                int c = wn + nt * 8 + g;
                bf[nt][0] = __float_as_uint(Bs[buf][kk + q][c]);
                bf[nt][1] = __float_as_uint(Bs[buf][kk + 4 + q][c]);
            }
            #pragma unroll
            for (int mt = 0; mt < 4; mt++)
                #pragma unroll
                for (int nt = 0; nt < 4; nt++) {
                    asm volatile(
                        "mma.sync.aligned.m16n8k8.row.col.f32.tf32.tf32.f32 "
                        "{%0,%1,%2,%3}, {%4,%5,%6,%7}, {%8,%9}, {%0,%1,%2,%3};"
                        : "+f"(acc[mt][nt][0]), "+f"(acc[mt][nt][1]),
                          "+f"(acc[mt][nt][2]), "+f"(acc[mt][nt][3])
                        : "r"(af[mt][0]), "r"(af[mt][1]), "r"(af[mt][2]), "r"(af[mt][3]),
                          "r"(bf[nt][0]), "r"(bf[nt][1]));
                }
        }

        if (has_next) {
            int nb = buf ^ 1;
            As[nb][akc + 0][arow] = __uint_as_float(f2tf32(a0.x));
            As[nb][akc + 1][arow] = __uint_as_float(f2tf32(a0.y));
            As[nb][akc + 2][arow] = __uint_as_float(f2tf32(a0.z));
            As[nb][akc + 3][arow] = __uint_as_float(f2tf32(a0.w));
            As[nb][akc + 0][arow + 64] = __uint_as_float(f2tf32(a1.x));
            As[nb][akc + 1][arow + 64] = __uint_as_float(f2tf32(a1.y));
            As[nb][akc + 2][arow + 64] = __uint_as_float(f2tf32(a1.z));
            As[nb][akc + 3][arow + 64] = __uint_as_float(f2tf32(a1.w));
            *(float4*)&Bs[nb][brow][bcol] = make_float4(
                __uint_as_float(f2tf32(b0.x)), __uint_as_float(f2tf32(b0.y)),
                __uint_as_float(f2tf32(b0.z)), __uint_as_float(f2tf32(b0.w)));
            *(float4*)&Bs[nb][brow + 8][bcol] = make_float4(
                __uint_as_float(f2tf32(b1.x)), __uint_as_float(f2tf32(b1.y)),
                __uint_as_float(f2tf32(b1.z)), __uint_as_float(f2tf32(b1.w)));
            __syncthreads();
            buf = nb;
        }
    }

    // epilogue: acc[mt][nt]: rows (row0+wm+mt*16+g, +8), cols (col0+wn+nt*8+2q, +1)
    #pragma unroll
    for (int mt = 0; mt < 4; mt++) {
        int r = row0 + wm + mt * 16 + g;
        #pragma unroll
        for (int nt = 0; nt < 4; nt++) {
            int c = col0 + wn + nt * 8 + 2 * q;
            float bv0 = bias[c], bv1 = bias[c + 1];
            float v00 = acc[mt][nt][0] + bv0;
            float v01 = acc[mt][nt][1] + bv1;
            float v10 = acc[mt][nt][2] + bv0;
            float v11 = acc[mt][nt][3] + bv1;
            if (EPI == 1) {
                v00 = 0.5f * v00 * (1.0f + erff(v00 * 0.70710678118654752f));
                v01 = 0.5f * v01 * (1.0f + erff(v01 * 0.70710678118654752f));
                v10 = 0.5f * v10 * (1.0f + erff(v10 * 0.70710678118654752f));
                v11 = 0.5f * v11 * (1.0f + erff(v11 * 0.70710678118654752f));
            }
            if (EPI == 2) {
                float2 r0 = *(const float2*)(res + (size_t)r * N + c);
                float2 r1 = *(const float2*)(res + (size_t)(r + 8) * N + c);
                v00 += r0.x; v01 += r0.y;
                v10 += r1.x; v11 += r1.y;
            }
            *(float2*)(C + (size_t)r * N + c)       = make_float2(v00, v01);
            *(float2*)(C + (size_t)(r + 8) * N + c) = make_float2(v10, v11);
        }
    }
}

// ---------------- flash attention: BQ=64, BKV=32, causal, GQA ----------------
__global__ __launch_bounds__(256)
void attn_kernel(const float* __restrict__ Q, const float* __restrict__ K,
                 const float* __restrict__ V, float* __restrict__ O)
{
    __shared__ float Qs[64][65];
    __shared__ float Ks[32][65];
    __shared__ float Vs[32][68];
    __shared__ float Ps[64][34];

    int tid = threadIdx.x;
    int qt = blockIdx.x;
    int bh = blockIdx.y;
    int b = bh >> 4;
    int h = bh & 15;
    int kvh = h >> 2;
    const float* Qb = Q + (size_t)(b * NHEAD + h)  * S_LEN * 64;
    const float* Kb = K + (size_t)(b * NKV  + kvh) * S_LEN * 64;
    const float* Vb = V + (size_t)(b * NKV  + kvh) * S_LEN * 64;
    int q0 = qt * 64;

    for (int i = tid; i < 64 * 16; i += 256) {
        int r = i >> 4, c = (i & 15) << 2;
        float4 v = *(const float4*)(Qb + (size_t)(q0 + r) * 64 + c);
        Qs[r][c] = v.x; Qs[r][c + 1] = v.y; Qs[r][c + 2] = v.z; Qs[r][c + 3] = v.w;
    }

    int tr = tid >> 4, tc = tid & 15;
    float m_run[4], l_run[4], o[4][4];
    #pragma unroll
    for (int i = 0; i < 4; i++) {
        m_run[i] = -INFINITY; l_run[i] = 0.f;
        #pragma unroll
        for (int j = 0; j < 4; j++) o[i][j] = 0.f;
    }

    int nkt = 2 * qt + 2;
    for (int jt = 0; jt < nkt; ++jt) {
        int j0 = jt * 32;
        __syncthreads();
        for (int i = tid; i < 32 * 16; i += 256) {
            int r = i >> 4, c = (i & 15) << 2;
            float4 kv = *(const float4*)(Kb + (size_t)(j0 + r) * 64 + c);
            Ks[r][c] = kv.x; Ks[r][c + 1] = kv.y; Ks[r][c + 2] = kv.z; Ks[r][c + 3] = kv.w;
            float4 vv = *(const float4*)(Vb + (size_t)(j0 + r) * 64 + c);
            Vs[r][c] = vv.x; Vs[r][c + 1] = vv.y; Vs[r][c + 2] = vv.z; Vs[r][c + 3] = vv.w;
        }
        __syncthreads();

        float s[4][2];
        #pragma unroll
        for (int i = 0; i < 4; i++) { s[i][0] = 0.f; s[i][1] = 0.f; }
        #pragma unroll 16
        for (int k = 0; k < 64; k++) {
            float a0 = Qs[tr * 4 + 0][k], a1 = Qs[tr * 4 + 1][k];
            float a2 = Qs[tr * 4 + 2][k], a3 = Qs[tr * 4 + 3][k];
            float b0 = Ks[tc * 2 + 0][k], b1 = Ks[tc * 2 + 1][k];
            s[0][0] += a0 * b0; s[0][1] += a0 * b1;
            s[1][0] += a1 * b0; s[1][1] += a1 * b1;
            s[2][0] += a2 * b0; s[2][1] += a2 * b1;
            s[3][0] += a3 * b0; s[3][1] += a3 * b1;
        }
        if (j0 + 31 > q0) {
            #pragma unroll
            for (int i = 0; i < 4; i++)
                #pragma unroll
                for (int j = 0; j < 2; j++)
                    if (j0 + tc * 2 + j > q0 + tr * 4 + i) s[i][j] = -INFINITY;
        }
        float mt[4];
        #pragma unroll
        for (int i = 0; i < 4; i++) mt[i] = fmaxf(s[i][0], s[i][1]);
        #pragma unroll
        for (int off = 1; off < 16; off <<= 1)
            #pragma unroll
            for (int i = 0; i < 4; i++)
                mt[i] = fmaxf(mt[i], __shfl_xor_sync(0xffffffffu, mt[i], off));
        float alpha[4], psum[4];
        #pragma unroll
        for (int i = 0; i < 4; i++) {
            float mn = fmaxf(m_run[i], mt[i]);
            alpha[i] = __expf(m_run[i] - mn);
            m_run[i] = mn;
            float p0 = __expf(s[i][0] - mn);
            float p1 = __expf(s[i][1] - mn);
            s[i][0] = p0; s[i][1] = p1;
            psum[i] = p0 + p1;
        }
        #pragma unroll
        for (int off = 1; off < 16; off <<= 1)
            #pragma unroll
            for (int i = 0; i < 4; i++)
                psum[i] += __shfl_xor_sync(0xffffffffu, psum[i], off);
        #pragma unroll
        for (int i = 0; i < 4; i++) {
            l_run[i] = l_run[i] * alpha[i] + psum[i];
            #pragma unroll
            for (int j = 0; j < 4; j++) o[i][j] *= alpha[i];
            *(float2*)&Ps[tr * 4 + i][tc * 2] = make_float2(s[i][0], s[i][1]);
        }
        __syncthreads();
        #pragma unroll 8
        for (int k = 0; k < 32; k++) {
            float4 vv = *(const float4*)&Vs[k][tc * 4];
            float p0 = Ps[tr * 4 + 0][k], p1 = Ps[tr * 4 + 1][k];
            float p2 = Ps[tr * 4 + 2][k], p3 = Ps[tr * 4 + 3][k];
            o[0][0] += p0 * vv.x; o[0][1] += p0 * vv.y; o[0][2] += p0 * vv.z; o[0][3] += p0 * vv.w;
            o[1][0] += p1 * vv.x; o[1][1] += p1 * vv.y; o[1][2] += p1 * vv.z; o[1][3] += p1 * vv.w;
            o[2][0] += p2 * vv.x; o[2][1] += p2 * vv.y; o[2][2] += p2 * vv.z; o[2][3] += p2 * vv.w;
            o[3][0] += p3 * vv.x; o[3][1] += p3 * vv.y; o[3][2] += p3 * vv.z; o[3][3] += p3 * vv.w;
        }
    }
    #pragma unroll
    for (int i = 0; i < 4; i++) {
        float inv = 1.0f / l_run[i];
        int srow = q0 + tr * 4 + i;
        float* dst = O + ((size_t)srow * BATCH + b) * DMODEL + h * 64 + tc * 4;
        *(float4*)dst = make_float4(o[i][0] * inv, o[i][1] * inv, o[i][2] * inv, o[i][3] * inv);
    }
}

// ---------------- host orchestration ----------------
extern "C" void kernel_launch(void* const* d_in, const int* in_sizes, int n_in,
                              void* d_out, int out_size)
{
    const float* x   = (const float*)d_in[0];
    const float* n1w = (const float*)d_in[1];
    const float* wq  = (const float*)d_in[2];
    const float* bq  = (const float*)d_in[3];
    const float* wk  = (const float*)d_in[4];
    const float* bk  = (const float*)d_in[5];
    const float* wv  = (const float*)d_in[6];
    const float* bv  = (const float*)d_in[7];
    const float* qnw = (const float*)d_in[8];
    const float* knw = (const float*)d_in[9];
    const float* wo  = (const float*)d_in[10];
    const float* bo  = (const float*)d_in[11];
    const float* n2w = (const float*)d_in[12];
    const float* w1  = (const float*)d_in[13];
    const float* b1  = (const float*)d_in[14];
    const float* w2  = (const float*)d_in[15];
    const float* b2  = (const float*)d_in[16];

    float *ph, *pwqkv, *pbqkv, *pqkv, *pq, *pk, *pv, *pattn, *px1, *ph2, *pmid;
    cudaGetSymbolAddress((void**)&ph,    g_h);
    cudaGetSymbolAddress((void**)&pwqkv, g_wqkv);
    cudaGetSymbolAddress((void**)&pbqkv, g_bqkv);
    cudaGetSymbolAddress((void**)&pqkv,  g_qkv);
    cudaGetSymbolAddress((void**)&pq,    g_q);
    cudaGetSymbolAddress((void**)&pk,    g_k);
    cudaGetSymbolAddress((void**)&pv,    g_v);
    cudaGetSymbolAddress((void**)&pattn, g_attn);
    cudaGetSymbolAddress((void**)&px1,   g_x1);
    cudaGetSymbolAddress((void**)&ph2,   g_h2);
    cudaGetSymbolAddress((void**)&pmid,  g_mid);

    pack_wqkv_kernel<<<(DMODEL * QKVN + 255) / 256, 256>>>(wq, wk, wv, bq, bk, bv, pwqkv, pbqkv);
    rmsnorm_kernel<<<NTOK, 256>>>(x, n1w, ph);
    gemm_tf32_kernel<0><<<dim3(QKVN / 128, NTOK / 128), 256>>>(ph, pwqkv, pbqkv, nullptr, pqkv,
                                                               NTOK, QKVN, DMODEL);
    qkrope_kernel<<<dim3(NTOK, 24), 64>>>(pqkv, qnw, knw, pq, pk, pv);
    attn_kernel<<<dim3(S_LEN / 64, BATCH * NHEAD), 256>>>(pq, pk, pv, pattn);
    gemm_tf32_kernel<2><<<dim3(DMODEL / 128, NTOK / 128), 256>>>(pattn, wo, bo, x, px1,
                                                                 NTOK, DMODEL, DMODEL);
    rmsnorm_kernel<<<NTOK, 256>>>(px1, n2w, ph2);
    gemm_tf32_kernel<1><<<dim3(DFF / 128, NTOK / 128), 256>>>(ph2, w1, b1, nullptr, pmid,
                                                              NTOK, DFF, DMODEL);
    gemm_tf32_kernel<2><<<dim3(DMODEL / 128, NTOK / 128), 256>>>(pmid, w2, b2, px1, (float*)d_out,
                                                                 NTOK, DMODEL, DFF);
}

// round 6
// speedup vs baseline: 2.9729x; 1.4795x over previous
#include <cuda_runtime.h>
#include <math.h>

#define S_LEN   2048
#define BATCH   2
#define DMODEL  1024
#define NHEAD   16
#define NKV     4
#define HEADDIM 64
#define NTOK    4096            // S_LEN * BATCH
#define DFF     4096            // 4 * DMODEL
#define QKVN    1536            // 1024 + 256 + 256
#define EPS_F   1e-5f
#define QK_SCALE 0.03125f       // D^-0.5 = 1/32

// attention smem layout (floats)
#define QS_STRIDE 68
#define KS_STRIDE 68
#define VS_STRIDE 72
#define ATTN_SMEM_FLOATS (64*QS_STRIDE + 64*KS_STRIDE + 64*VS_STRIDE)
#define ATTN_SMEM_BYTES  (ATTN_SMEM_FLOATS * 4)

// ---------------- scratch (__device__ globals; no allocation allowed) ----------------
__device__ float g_h   [NTOK * DMODEL];
__device__ float g_wqkv[DMODEL * QKVN];
__device__ float g_bqkv[QKVN];
__device__ float g_qkv [NTOK * QKVN];
__device__ float g_q   [BATCH * NHEAD * S_LEN * HEADDIM];
__device__ float g_k   [BATCH * NKV   * S_LEN * HEADDIM];
__device__ float g_v   [BATCH * NKV   * S_LEN * HEADDIM];
__device__ float g_attn[NTOK * DMODEL];
__device__ float g_x1  [NTOK * DMODEL];
__device__ float g_h2  [NTOK * DMODEL];
__device__ float g_mid [NTOK * DFF];

__device__ __forceinline__ unsigned f2tf32(float x) {
    unsigned u;
    asm("cvt.rna.tf32.f32 %0, %1;" : "=r"(u) : "f"(x));
    return u;
}

// ---------------- pack wq|wk|wv into one [D, 1536] weight ----------------
__global__ void pack_wqkv_kernel(const float* __restrict__ wq, const float* __restrict__ wk,
                                 const float* __restrict__ wv, const float* __restrict__ bq,
                                 const float* __restrict__ bk, const float* __restrict__ bv,
                                 float* __restrict__ W, float* __restrict__ bias)
{
    int idx = blockIdx.x * 256 + threadIdx.x;
    if (idx < DMODEL * QKVN) {
        int k = idx / QKVN, c = idx % QKVN;
        float v;
        if (c < 1024)       v = wq[k * 1024 + c];
        else if (c < 1280)  v = wk[k * 256 + (c - 1024)];
        else                v = wv[k * 256 + (c - 1280)];
        W[idx] = v;
    }
    if (idx < QKVN) {
        bias[idx] = (idx < 1024) ? bq[idx] : (idx < 1280 ? bk[idx - 1024] : bv[idx - 1280]);
    }
}

// ---------------- RMSNorm over D=1024, one block per row ----------------
__global__ __launch_bounds__(256)
void rmsnorm_kernel(const float* __restrict__ x, const float* __restrict__ w,
                    float* __restrict__ y)
{
    int row = blockIdx.x;
    int i = threadIdx.x;
    const float* xr = x + (size_t)row * DMODEL;
    float4 xv = *(const float4*)(xr + i * 4);
    float ss = xv.x * xv.x + xv.y * xv.y + xv.z * xv.z + xv.w * xv.w;
    #pragma unroll
    for (int off = 16; off; off >>= 1) ss += __shfl_xor_sync(0xffffffffu, ss, off);
    __shared__ float red[8];
    __shared__ float s_sc;
    if ((i & 31) == 0) red[i >> 5] = ss;
    __syncthreads();
    if (i == 0) {
        float tot = 0.f;
        #pragma unroll
        for (int kk = 0; kk < 8; kk++) tot += red[kk];
        s_sc = rsqrtf(tot * (1.0f / DMODEL) + EPS_F);
    }
    __syncthreads();
    float sc = s_sc;
    float4 wv = *(const float4*)(w + i * 4);
    float4 ov = make_float4(xv.x * sc * wv.x, xv.y * sc * wv.y,
                            xv.z * sc * wv.z, xv.w * sc * wv.w);
    *(float4*)(y + (size_t)row * DMODEL + i * 4) = ov;
}

// ---------------- per-head QK RMSNorm + RoPE + relayout; V relayout ----------------
__global__ __launch_bounds__(64)
void qkrope_kernel(const float* __restrict__ qkv, const float* __restrict__ qn_w,
                   const float* __restrict__ kn_w, float* __restrict__ Qo,
                   float* __restrict__ Ko, float* __restrict__ Vo)
{
    int t = blockIdx.x;            // token = s*BATCH + b
    int slot = blockIdx.y;
    int i = threadIdx.x;           // 0..63
    int s = t / BATCH, b = t % BATCH;
    __shared__ float buf[64];
    __shared__ float red[2];

    if (slot >= 20) {   // V: pure relayout
        int vh = slot - 20;
        float v = qkv[(size_t)t * QKVN + 1280 + vh * 64 + i];
        Vo[((size_t)(b * NKV + vh) * S_LEN + s) * 64 + i] = v;
        return;
    }

    bool is_q = (slot < 16);
    int col = is_q ? (slot * 64 + i) : (1024 + (slot - 16) * 64 + i);
    float v = qkv[(size_t)t * QKVN + col];
    float ss = v * v;
    #pragma unroll
    for (int off = 16; off; off >>= 1) ss += __shfl_xor_sync(0xffffffffu, ss, off);
    if ((i & 31) == 0) red[i >> 5] = ss;
    __syncthreads();
    float tot = red[0] + red[1];
    float sc = rsqrtf(tot * (1.0f / 64.0f) + EPS_F);
    const float* w = is_q ? qn_w : kn_w;
    float nv = v * sc * w[i];
    buf[i] = nv;
    __syncthreads();
    float rot = (i < 32) ? -buf[i + 32] : buf[i - 32];
    int j = i & 31;
    float invf = exp2f(-(float)j * (13.287712379549449f / 32.0f));
    float ang = (float)s * invf;
    float sn, cs;
    sincosf(ang, &sn, &cs);
    float outv = nv * cs + rot * sn;
    if (is_q) {
        outv *= QK_SCALE;
        Qo[((size_t)(b * NHEAD + slot) * S_LEN + s) * 64 + i] = outv;
    } else {
        Ko[((size_t)(b * NKV + (slot - 16)) * S_LEN + s) * 64 + i] = outv;
    }
}

// ---------------- TF32 tensor-core GEMM (unchanged from R4) ----------------
template<int EPI>
__global__ __launch_bounds__(256)
void gemm_tf32_kernel(const float* __restrict__ A, const float* __restrict__ B,
                      const float* __restrict__ bias, const float* __restrict__ res,
                      float* __restrict__ C, int M, int N, int K)
{
    __shared__ float As[2][16][136];
    __shared__ float Bs[2][16][136];

    int tid  = threadIdx.x;
    int wid  = tid >> 5, lane = tid & 31;
    int g    = lane >> 2;
    int q    = lane & 3;
    int wm   = (wid >> 2) * 64;
    int wn   = (wid & 3) * 32;

    int row0 = blockIdx.y * 128;
    int col0 = blockIdx.x * 128;

    int arow = tid >> 2;
    int akc  = (tid & 3) << 2;
    const float* Ap = A + (size_t)(row0 + arow) * K + akc;
    int brow = tid >> 5;
    int bcol = (tid & 31) << 2;
    const float* Bp = B + (size_t)brow * N + col0 + bcol;

    float acc[4][4][4];
    #pragma unroll
    for (int mt = 0; mt < 4; mt++)
        #pragma unroll
        for (int nt = 0; nt < 4; nt++)
            #pragma unroll
            for (int r = 0; r < 4; r++) acc[mt][nt][r] = 0.f;

    {
        float4 a0 = *(const float4*)Ap;
        float4 a1 = *(const float4*)(Ap + (size_t)64 * K);
        float4 b0 = *(const float4*)Bp;
        float4 b1 = *(const float4*)(Bp + (size_t)8 * N);
        As[0][akc + 0][arow] = __uint_as_float(f2tf32(a0.x));
        As[0][akc + 1][arow] = __uint_as_float(f2tf32(a0.y));
        As[0][akc + 2][arow] = __uint_as_float(f2tf32(a0.z));
        As[0][akc + 3][arow] = __uint_as_float(f2tf32(a0.w));
        As[0][akc + 0][arow + 64] = __uint_as_float(f2tf32(a1.x));
        As[0][akc + 1][arow + 64] = __uint_as_float(f2tf32(a1.y));
        As[0][akc + 2][arow + 64] = __uint_as_float(f2tf32(a1.z));
        As[0][akc + 3][arow + 64] = __uint_as_float(f2tf32(a1.w));
        *(float4*)&Bs[0][brow][bcol] = make_float4(
            __uint_as_float(f2tf32(b0.x)), __uint_as_float(f2tf32(b0.y)),
            __uint_as_float(f2tf32(b0.z)), __uint_as_float(f2tf32(b0.w)));
        *(float4*)&Bs[0][brow + 8][bcol] = make_float4(
            __uint_as_float(f2tf32(b1.x)), __uint_as_float(f2tf32(b1.y)),
            __uint_as_float(f2tf32(b1.z)), __uint_as_float(f2tf32(b1.w)));
    }
    __syncthreads();

    int buf = 0;
    for (int k0 = 0; k0 < K; k0 += 16) {
        bool has_next = (k0 + 16) < K;
        float4 a0, a1, b0, b1;
        if (has_next) {
            a0 = *(const float4*)(Ap + k0 + 16);
            a1 = *(const float4*)(Ap + (size_t)64 * K + k0 + 16);
            b0 = *(const float4*)(Bp + (size_t)(k0 + 16) * N);
            b1 = *(const float4*)(Bp + (size_t)(k0 + 24) * N);
        }

        #pragma unroll
        for (int kk = 0; kk < 16; kk += 8) {
            unsigned af[4][4];
            #pragma unroll
            for (int mt = 0; mt < 4; mt++) {
                int r = wm + mt * 16 + g;
                af[mt][0] = __float_as_uint(As[buf][kk + q][r]);
                af[mt][1] = __float_as_uint(As[buf][kk + q][r + 8]);
                af[mt][2] = __float_as_uint(As[buf][kk + 4 + q][r]);
                af[mt][3] = __float_as_uint(As[buf][kk + 4 + q][r + 8]);
            }
            unsigned bf[4][2];
            #pragma unroll
            for (int nt = 0; nt < 4; nt++) {
                int c = wn + nt * 8 + g;
                bf[nt][0] = __float_as_uint(Bs[buf][kk + q][c]);
                bf[nt][1] = __float_as_uint(Bs[buf][kk + 4 + q][c]);
            }
            #pragma unroll
            for (int mt = 0; mt < 4; mt++)
                #pragma unroll
                for (int nt = 0; nt < 4; nt++) {
                    asm volatile(
                        "mma.sync.aligned.m16n8k8.row.col.f32.tf32.tf32.f32 "
                        "{%0,%1,%2,%3}, {%4,%5,%6,%7}, {%8,%9}, {%0,%1,%2,%3};"
                        : "+f"(acc[mt][nt][0]), "+f"(acc[mt][nt][1]),
                          "+f"(acc[mt][nt][2]), "+f"(acc[mt][nt][3])
                        : "r"(af[mt][0]), "r"(af[mt][1]), "r"(af[mt][2]), "r"(af[mt][3]),
                          "r"(bf[nt][0]), "r"(bf[nt][1]));
                }
        }

        if (has_next) {
            int nb = buf ^ 1;
            As[nb][akc + 0][arow] = __uint_as_float(f2tf32(a0.x));
            As[nb][akc + 1][arow] = __uint_as_float(f2tf32(a0.y));
            As[nb][akc + 2][arow] = __uint_as_float(f2tf32(a0.z));
            As[nb][akc + 3][arow] = __uint_as_float(f2tf32(a0.w));
            As[nb][akc + 0][arow + 64] = __uint_as_float(f2tf32(a1.x));
            As[nb][akc + 1][arow + 64] = __uint_as_float(f2tf32(a1.y));
            As[nb][akc + 2][arow + 64] = __uint_as_float(f2tf32(a1.z));
            As[nb][akc + 3][arow + 64] = __uint_as_float(f2tf32(a1.w));
            *(float4*)&Bs[nb][brow][bcol] = make_float4(
                __uint_as_float(f2tf32(b0.x)), __uint_as_float(f2tf32(b0.y)),
                __uint_as_float(f2tf32(b0.z)), __uint_as_float(f2tf32(b0.w)));
            *(float4*)&Bs[nb][brow + 8][bcol] = make_float4(
                __uint_as_float(f2tf32(b1.x)), __uint_as_float(f2tf32(b1.y)),
                __uint_as_float(f2tf32(b1.z)), __uint_as_float(f2tf32(b1.w)));
            __syncthreads();
            buf = nb;
        }
    }

    #pragma unroll
    for (int mt = 0; mt < 4; mt++) {
        int r = row0 + wm + mt * 16 + g;
        #pragma unroll
        for (int nt = 0; nt < 4; nt++) {
            int c = col0 + wn + nt * 8 + 2 * q;
            float bv0 = bias[c], bv1 = bias[c + 1];
            float v00 = acc[mt][nt][0] + bv0;
            float v01 = acc[mt][nt][1] + bv1;
            float v10 = acc[mt][nt][2] + bv0;
            float v11 = acc[mt][nt][3] + bv1;
            if (EPI == 1) {
                v00 = 0.5f * v00 * (1.0f + erff(v00 * 0.70710678118654752f));
                v01 = 0.5f * v01 * (1.0f + erff(v01 * 0.70710678118654752f));
                v10 = 0.5f * v10 * (1.0f + erff(v10 * 0.70710678118654752f));
                v11 = 0.5f * v11 * (1.0f + erff(v11 * 0.70710678118654752f));
            }
            if (EPI == 2) {
                float2 r0 = *(const float2*)(res + (size_t)r * N + c);
                float2 r1 = *(const float2*)(res + (size_t)(r + 8) * N + c);
                v00 += r0.x; v01 += r0.y;
                v10 += r1.x; v11 += r1.y;
            }
            *(float2*)(C + (size_t)r * N + c)       = make_float2(v00, v01);
            *(float2*)(C + (size_t)(r + 8) * N + c) = make_float2(v10, v11);
        }
    }
}

// ---------------- TF32 tensor-core flash attention ----------------
// BQ=64, BKV=64, 4 warps (warp w owns q-rows 16w..16w+15), causal, GQA.
// Q pre-scaled by QK_SCALE. QK^T and P*V both on mma.sync.m16n8k8 tf32.
// P (score C-fragments) redistributed to A-fragment layout via warp shuffles.
__global__ __launch_bounds__(128)
void attn_tc_kernel(const float* __restrict__ Q, const float* __restrict__ K,
                    const float* __restrict__ V, float* __restrict__ O)
{
    extern __shared__ float sm[];
    float* Qs = sm;                                  // [64][QS_STRIDE]
    float* Ks = sm + 64 * QS_STRIDE;                 // [64][KS_STRIDE]
    float* Vs = sm + 64 * (QS_STRIDE + KS_STRIDE);   // [64][VS_STRIDE]

    int tid  = threadIdx.x;
    int wid  = tid >> 5, lane = tid & 31;
    int g    = lane >> 2;          // 0..7
    int q    = lane & 3;           // 0..3
    int qt   = blockIdx.x;
    int bh   = blockIdx.y;
    int b    = bh >> 4;
    int h    = bh & 15;
    int kvh  = h >> 2;
    int q0   = qt * 64;

    const float* Qb = Q + (size_t)(b * NHEAD + h)  * S_LEN * 64 + (size_t)q0 * 64;
    const float* Kb = K + (size_t)(b * NKV  + kvh) * S_LEN * 64;
    const float* Vb = V + (size_t)(b * NKV  + kvh) * S_LEN * 64;

    // stage Q (tf32-converted)
    for (int i = tid; i < 64 * 16; i += 128) {
        int r = i >> 4, c = (i & 15) << 2;
        float4 v = *(const float4*)(Qb + (size_t)r * 64 + c);
        *(float4*)&Qs[r * QS_STRIDE + c] = make_float4(
            __uint_as_float(f2tf32(v.x)), __uint_as_float(f2tf32(v.y)),
            __uint_as_float(f2tf32(v.z)), __uint_as_float(f2tf32(v.w)));
    }

    float m0 = -INFINITY, m1 = -INFINITY, l0 = 0.f, l1 = 0.f;
    float o[8][4];
    #pragma unroll
    for (int nt = 0; nt < 8; nt++)
        #pragma unroll
        for (int r = 0; r < 4; r++) o[nt][r] = 0.f;

    int row_a = 16 * wid + g;      // local q row (fragment row g)
    int nkt = qt + 1;

    for (int jt = 0; jt < nkt; ++jt) {
        int j0 = jt * 64;
        __syncthreads();
        for (int i = tid; i < 64 * 16; i += 128) {
            int r = i >> 4, c = (i & 15) << 2;
            float4 kv = *(const float4*)(Kb + (size_t)(j0 + r) * 64 + c);
            *(float4*)&Ks[r * KS_STRIDE + c] = make_float4(
                __uint_as_float(f2tf32(kv.x)), __uint_as_float(f2tf32(kv.y)),
                __uint_as_float(f2tf32(kv.z)), __uint_as_float(f2tf32(kv.w)));
            float4 vv = *(const float4*)(Vb + (size_t)(j0 + r) * 64 + c);
            *(float4*)&Vs[r * VS_STRIDE + c] = make_float4(
                __uint_as_float(f2tf32(vv.x)), __uint_as_float(f2tf32(vv.y)),
                __uint_as_float(f2tf32(vv.z)), __uint_as_float(f2tf32(vv.w)));
        }
        __syncthreads();

        // ---- S = Q K^T (m16 x n64 per warp) ----
        float s[8][4];
        #pragma unroll
        for (int nt = 0; nt < 8; nt++)
            #pragma unroll
            for (int r = 0; r < 4; r++) s[nt][r] = 0.f;

        #pragma unroll
        for (int k0 = 0; k0 < 64; k0 += 8) {
            unsigned a0 = __float_as_uint(Qs[(row_a)     * QS_STRIDE + k0 + q]);
            unsigned a1 = __float_as_uint(Qs[(row_a + 8) * QS_STRIDE + k0 + q]);
            unsigned a2 = __float_as_uint(Qs[(row_a)     * QS_STRIDE + k0 + q + 4]);
            unsigned a3 = __float_as_uint(Qs[(row_a + 8) * QS_STRIDE + k0 + q + 4]);
            #pragma unroll
            for (int nt = 0; nt < 8; nt++) {
                unsigned b0 = __float_as_uint(Ks[(nt * 8 + g) * KS_STRIDE + k0 + q]);
                unsigned b1 = __float_as_uint(Ks[(nt * 8 + g) * KS_STRIDE + k0 + q + 4]);
                asm volatile(
                    "mma.sync.aligned.m16n8k8.row.col.f32.tf32.tf32.f32 "
                    "{%0,%1,%2,%3}, {%4,%5,%6,%7}, {%8,%9}, {%0,%1,%2,%3};"
                    : "+f"(s[nt][0]), "+f"(s[nt][1]), "+f"(s[nt][2]), "+f"(s[nt][3])
                    : "r"(a0), "r"(a1), "r"(a2), "r"(a3), "r"(b0), "r"(b1));
            }
        }

        // ---- causal mask (diagonal tile only; j0 == q0 there) ----
        if (jt == qt) {
            #pragma unroll
            for (int nt = 0; nt < 8; nt++) {
                int col = nt * 8 + 2 * q;
                if (col     > row_a)     s[nt][0] = -INFINITY;
                if (col + 1 > row_a)     s[nt][1] = -INFINITY;
                if (col     > row_a + 8) s[nt][2] = -INFINITY;
                if (col + 1 > row_a + 8) s[nt][3] = -INFINITY;
            }
        }

        // ---- online softmax (rows g and g+8; owners = 4-lane q-group) ----
        float mt0 = -INFINITY, mt1 = -INFINITY;
        #pragma unroll
        for (int nt = 0; nt < 8; nt++) {
            mt0 = fmaxf(mt0, fmaxf(s[nt][0], s[nt][1]));
            mt1 = fmaxf(mt1, fmaxf(s[nt][2], s[nt][3]));
        }
        #pragma unroll
        for (int off = 1; off < 4; off <<= 1) {
            mt0 = fmaxf(mt0, __shfl_xor_sync(0xffffffffu, mt0, off));
            mt1 = fmaxf(mt1, __shfl_xor_sync(0xffffffffu, mt1, off));
        }
        float mn0 = fmaxf(m0, mt0), mn1 = fmaxf(m1, mt1);
        float al0 = __expf(m0 - mn0), al1 = __expf(m1 - mn1);
        m0 = mn0; m1 = mn1;
        float ps0 = 0.f, ps1 = 0.f;
        #pragma unroll
        for (int nt = 0; nt < 8; nt++) {
            s[nt][0] = __expf(s[nt][0] - mn0);
            s[nt][1] = __expf(s[nt][1] - mn0);
            s[nt][2] = __expf(s[nt][2] - mn1);
            s[nt][3] = __expf(s[nt][3] - mn1);
            ps0 += s[nt][0] + s[nt][1];
            ps1 += s[nt][2] + s[nt][3];
            o[nt][0] *= al0; o[nt][1] *= al0;
            o[nt][2] *= al1; o[nt][3] *= al1;
        }
        #pragma unroll
        for (int off = 1; off < 4; off <<= 1) {
            ps0 += __shfl_xor_sync(0xffffffffu, ps0, off);
            ps1 += __shfl_xor_sync(0xffffffffu, ps1, off);
        }
        l0 = l0 * al0 + ps0;
        l1 = l1 * al1 + ps1;

        // ---- O += P V (A frags from P via shuffles) ----
        int base  = lane & ~3;
        int srcLo = base + (q >> 1);
        int srcHi = base + 2 + (q >> 1);
        bool odd  = q & 1;
        #pragma unroll
        for (int kc = 0; kc < 8; kc++) {
            float p0 = s[kc][0], p1 = s[kc][1], p2 = s[kc][2], p3 = s[kc][3];
            float t0 = __shfl_sync(0xffffffffu, p0, srcLo);
            float t1 = __shfl_sync(0xffffffffu, p1, srcLo);
            float t2 = __shfl_sync(0xffffffffu, p2, srcLo);
            float t3 = __shfl_sync(0xffffffffu, p3, srcLo);
            float u0 = __shfl_sync(0xffffffffu, p0, srcHi);
            float u1 = __shfl_sync(0xffffffffu, p1, srcHi);
            float u2 = __shfl_sync(0xffffffffu, p2, srcHi);
            float u3 = __shfl_sync(0xffffffffu, p3, srcHi);
            unsigned a0 = f2tf32(odd ? t1 : t0);
            unsigned a1 = f2tf32(odd ? t3 : t2);
            unsigned a2 = f2tf32(odd ? u1 : u0);
            unsigned a3 = f2tf32(odd ? u3 : u2);
            #pragma unroll
            for (int nt = 0; nt < 8; nt++) {
                unsigned b0 = __float_as_uint(Vs[(kc * 8 + q)     * VS_STRIDE + nt * 8 + g]);
                unsigned b1 = __float_as_uint(Vs[(kc * 8 + q + 4) * VS_STRIDE + nt * 8 + g]);
                asm volatile(
                    "mma.sync.aligned.m16n8k8.row.col.f32.tf32.tf32.f32 "
                    "{%0,%1,%2,%3}, {%4,%5,%6,%7}, {%8,%9}, {%0,%1,%2,%3};"
                    : "+f"(o[nt][0]), "+f"(o[nt][1]), "+f"(o[nt][2]), "+f"(o[nt][3])
                    : "r"(a0), "r"(a1), "r"(a2), "r"(a3), "r"(b0), "r"(b1));
            }
        }
    }

    // ---- epilogue: normalize, write [token, D] with token = s*BATCH + b ----
    float inv0 = 1.0f / l0, inv1 = 1.0f / l1;
    int srow0 = q0 + row_a;
    int srow1 = srow0 + 8;
    #pragma unroll
    for (int nt = 0; nt < 8; nt++) {
        int c = h * 64 + nt * 8 + 2 * q;
        *(float2*)(O + ((size_t)srow0 * BATCH + b) * DMODEL + c) =
            make_float2(o[nt][0] * inv0, o[nt][1] * inv0);
        *(float2*)(O + ((size_t)srow1 * BATCH + b) * DMODEL + c) =
            make_float2(o[nt][2] * inv1, o[nt][3] * inv1);
    }
}

// ---------------- host orchestration ----------------
extern "C" void kernel_launch(void* const* d_in, const int* in_sizes, int n_in,
                              void* d_out, int out_size)
{
    const float* x   = (const float*)d_in[0];
    const float* n1w = (const float*)d_in[1];
    const float* wq  = (const float*)d_in[2];
    const float* bq  = (const float*)d_in[3];
    const float* wk  = (const float*)d_in[4];
    const float* bk  = (const float*)d_in[5];
    const float* wv  = (const float*)d_in[6];
    const float* bv  = (const float*)d_in[7];
    const float* qnw = (const float*)d_in[8];
    const float* knw = (const float*)d_in[9];
    const float* wo  = (const float*)d_in[10];
    const float* bo  = (const float*)d_in[11];
    const float* n2w = (const float*)d_in[12];
    const float* w1  = (const float*)d_in[13];
    const float* b1  = (const float*)d_in[14];
    const float* w2  = (const float*)d_in[15];
    const float* b2  = (const float*)d_in[16];

    float *ph, *pwqkv, *pbqkv, *pqkv, *pq, *pk, *pv, *pattn, *px1, *ph2, *pmid;
    cudaGetSymbolAddress((void**)&ph,    g_h);
    cudaGetSymbolAddress((void**)&pwqkv, g_wqkv);
    cudaGetSymbolAddress((void**)&pbqkv, g_bqkv);
    cudaGetSymbolAddress((void**)&pqkv,  g_qkv);
    cudaGetSymbolAddress((void**)&pq,    g_q);
    cudaGetSymbolAddress((void**)&pk,    g_k);
    cudaGetSymbolAddress((void**)&pv,    g_v);
    cudaGetSymbolAddress((void**)&pattn, g_attn);
    cudaGetSymbolAddress((void**)&px1,   g_x1);
    cudaGetSymbolAddress((void**)&ph2,   g_h2);
    cudaGetSymbolAddress((void**)&pmid,  g_mid);

    cudaFuncSetAttribute(attn_tc_kernel,
                         cudaFuncAttributeMaxDynamicSharedMemorySize, ATTN_SMEM_BYTES);

    pack_wqkv_kernel<<<(DMODEL * QKVN + 255) / 256, 256>>>(wq, wk, wv, bq, bk, bv, pwqkv, pbqkv);
    rmsnorm_kernel<<<NTOK, 256>>>(x, n1w, ph);
    gemm_tf32_kernel<0><<<dim3(QKVN / 128, NTOK / 128), 256>>>(ph, pwqkv, pbqkv, nullptr, pqkv,
                                                               NTOK, QKVN, DMODEL);
    qkrope_kernel<<<dim3(NTOK, 24), 64>>>(pqkv, qnw, knw, pq, pk, pv);
    attn_tc_kernel<<<dim3(S_LEN / 64, BATCH * NHEAD), 128, ATTN_SMEM_BYTES>>>(pq, pk, pv, pattn);
    gemm_tf32_kernel<2><<<dim3(DMODEL / 128, NTOK / 128), 256>>>(pattn, wo, bo, x, px1,
                                                                 NTOK, DMODEL, DMODEL);
    rmsnorm_kernel<<<NTOK, 256>>>(px1, n2w, ph2);
    gemm_tf32_kernel<1><<<dim3(DFF / 128, NTOK / 128), 256>>>(ph2, w1, b1, nullptr, pmid,
                                                              NTOK, DFF, DMODEL);
    gemm_tf32_kernel<2><<<dim3(DMODEL / 128, NTOK / 128), 256>>>(pmid, w2, b2, px1, (float*)d_out,
                                                                 NTOK, DMODEL, DFF);
}

// round 7
// speedup vs baseline: 3.2086x; 1.0793x over previous
#include <cuda_runtime.h>
#include <math.h>

#define S_LEN   2048
#define BATCH   2
#define DMODEL  1024
#define NHEAD   16
#define NKV     4
#define HEADDIM 64
#define NTOK    4096            // S_LEN * BATCH
#define DFF     4096            // 4 * DMODEL
#define QKVN    1536            // 1024 + 256 + 256
#define EPS_F   1e-5f
#define QK_SCALE 0.03125f       // D^-0.5 = 1/32

// attention smem layout (floats)
#define QS_STRIDE 68
#define KS_STRIDE 68
#define VS_STRIDE 72
#define ATTN_SMEM_FLOATS (64*QS_STRIDE + 64*KS_STRIDE + 64*VS_STRIDE)
#define ATTN_SMEM_BYTES  (ATTN_SMEM_FLOATS * 4)

// GEMM smem: 4 stages, A tile 128x16 stored [m][20], B tile 16x128 stored [k][136]
#define AS_TILE 2560            // 128*20 floats
#define BS_TILE 2176            // 16*136 floats
#define GEMM_STAGES 4
#define GEMM_SMEM_FLOATS (GEMM_STAGES * (AS_TILE + BS_TILE))
#define GEMM_SMEM_BYTES  (GEMM_SMEM_FLOATS * 4)

// ---------------- scratch (__device__ globals; no allocation allowed) ----------------
__device__ float g_h   [NTOK * DMODEL];
__device__ float g_wqkv[DMODEL * QKVN];
__device__ float g_bqkv[QKVN];
__device__ float g_qkv [NTOK * QKVN];
__device__ float g_q   [BATCH * NHEAD * S_LEN * HEADDIM];
__device__ float g_k   [BATCH * NKV   * S_LEN * HEADDIM];
__device__ float g_v   [BATCH * NKV   * S_LEN * HEADDIM];
__device__ float g_attn[NTOK * DMODEL];
__device__ float g_x1  [NTOK * DMODEL];
__device__ float g_h2  [NTOK * DMODEL];
__device__ float g_mid [NTOK * DFF];
__device__ float g_wor [DMODEL * DMODEL];
__device__ float g_w1r [DMODEL * DFF];
__device__ float g_w2r [DFF * DMODEL];

__device__ __forceinline__ unsigned f2tf32(float x) {
    unsigned u;
    asm("cvt.rna.tf32.f32 %0, %1;" : "=r"(u) : "f"(x));
    return u;
}
__device__ __forceinline__ float tf32r(float x) { return __uint_as_float(f2tf32(x)); }

__device__ __forceinline__ void cp16(float* dst_smem, const float* src) {
    unsigned d = (unsigned)__cvta_generic_to_shared(dst_smem);
    asm volatile("cp.async.ca.shared.global [%0], [%1], 16;" :: "r"(d), "l"(src));
}
__device__ __forceinline__ void cp_commit() {
    asm volatile("cp.async.commit_group;" ::: "memory");
}
__device__ __forceinline__ void cp_wait2() {
    asm volatile("cp.async.wait_group 2;" ::: "memory");
}

// ---------------- round-to-tf32 copy (for wo, w1, w2) ----------------
__global__ __launch_bounds__(256)
void roundcopy_kernel(const float* __restrict__ src, float* __restrict__ dst, int n4)
{
    int i = blockIdx.x * 256 + threadIdx.x;
    if (i < n4) {
        float4 v = ((const float4*)src)[i];
        ((float4*)dst)[i] = make_float4(tf32r(v.x), tf32r(v.y), tf32r(v.z), tf32r(v.w));
    }
}

// ---------------- pack wq|wk|wv into one [D, 1536] weight (tf32-rounded) ----------------
__global__ void pack_wqkv_kernel(const float* __restrict__ wq, const float* __restrict__ wk,
                                 const float* __restrict__ wv, const float* __restrict__ bq,
                                 const float* __restrict__ bk, const float* __restrict__ bv,
                                 float* __restrict__ W, float* __restrict__ bias)
{
    int idx = blockIdx.x * 256 + threadIdx.x;
    if (idx < DMODEL * QKVN) {
        int k = idx / QKVN, c = idx % QKVN;
        float v;
        if (c < 1024)       v = wq[k * 1024 + c];
        else if (c < 1280)  v = wk[k * 256 + (c - 1024)];
        else                v = wv[k * 256 + (c - 1280)];
        W[idx] = tf32r(v);
    }
    if (idx < QKVN) {
        bias[idx] = (idx < 1024) ? bq[idx] : (idx < 1280 ? bk[idx - 1024] : bv[idx - 1280]);
    }
}

// ---------------- RMSNorm over D=1024 (output tf32-rounded; feeds GEMM A) ----------------
__global__ __launch_bounds__(256)
void rmsnorm_kernel(const float* __restrict__ x, const float* __restrict__ w,
                    float* __restrict__ y)
{
    int row = blockIdx.x;
    int i = threadIdx.x;
    const float* xr = x + (size_t)row * DMODEL;
    float4 xv = *(const float4*)(xr + i * 4);
    float ss = xv.x * xv.x + xv.y * xv.y + xv.z * xv.z + xv.w * xv.w;
    #pragma unroll
    for (int off = 16; off; off >>= 1) ss += __shfl_xor_sync(0xffffffffu, ss, off);
    __shared__ float red[8];
    __shared__ float s_sc;
    if ((i & 31) == 0) red[i >> 5] = ss;
    __syncthreads();
    if (i == 0) {
        float tot = 0.f;
        #pragma unroll
        for (int kk = 0; kk < 8; kk++) tot += red[kk];
        s_sc = rsqrtf(tot * (1.0f / DMODEL) + EPS_F);
    }
    __syncthreads();
    float sc = s_sc;
    float4 wv = *(const float4*)(w + i * 4);
    float4 ov = make_float4(tf32r(xv.x * sc * wv.x), tf32r(xv.y * sc * wv.y),
                            tf32r(xv.z * sc * wv.z), tf32r(xv.w * sc * wv.w));
    *(float4*)(y + (size_t)row * DMODEL + i * 4) = ov;
}

// ---------------- per-head QK RMSNorm + RoPE + relayout; V relayout ----------------
// block (64,4): 4 slots per block, grid (NTOK, 6). Slot type uniform within a block.
__global__ __launch_bounds__(256)
void qkrope_kernel(const float* __restrict__ qkv, const float* __restrict__ qn_w,
                   const float* __restrict__ kn_w, float* __restrict__ Qo,
                   float* __restrict__ Ko, float* __restrict__ Vo)
{
    int t = blockIdx.x;            // token = s*BATCH + b
    int ty = threadIdx.y;          // 0..3
    int slot = blockIdx.y * 4 + ty;
    int i = threadIdx.x;           // 0..63
    int s = t / BATCH, b = t % BATCH;
    __shared__ float buf[4][64];
    __shared__ float red[4][2];

    if (slot >= 20) {   // V: pure relayout (whole block is V)
        int vh = slot - 20;
        float v = qkv[(size_t)t * QKVN + 1280 + vh * 64 + i];
        Vo[((size_t)(b * NKV + vh) * S_LEN + s) * 64 + i] = v;
        return;
    }

    bool is_q = (slot < 16);
    int col = is_q ? (slot * 64 + i) : (1024 + (slot - 16) * 64 + i);
    float v = qkv[(size_t)t * QKVN + col];
    float ss = v * v;
    #pragma unroll
    for (int off = 16; off; off >>= 1) ss += __shfl_xor_sync(0xffffffffu, ss, off);
    if ((i & 31) == 0) red[ty][i >> 5] = ss;
    __syncthreads();
    float tot = red[ty][0] + red[ty][1];
    float sc = rsqrtf(tot * (1.0f / 64.0f) + EPS_F);
    const float* w = is_q ? qn_w : kn_w;
    float nv = v * sc * w[i];
    buf[ty][i] = nv;
    __syncthreads();
    float rot = (i < 32) ? -buf[ty][i + 32] : buf[ty][i - 32];
    int j = i & 31;
    float invf = exp2f(-(float)j * (13.287712379549449f / 32.0f));
    float ang = (float)s * invf;
    float sn, cs;
    sincosf(ang, &sn, &cs);
    float outv = nv * cs + rot * sn;
    if (is_q) {
        outv *= QK_SCALE;
        Qo[((size_t)(b * NHEAD + slot) * S_LEN + s) * 64 + i] = outv;
    } else {
        Ko[((size_t)(b * NKV + (slot - 16)) * S_LEN + s) * 64 + i] = outv;
    }
}

// ---------------- TF32 GEMM, 4-stage cp.async pipeline ----------------
// A and B MUST already be tf32-rounded (raw bits copied to smem).
// EPI: 0 = +bias, 1 = gelu(+bias) tf32-rounded out, 2 = +bias + residual
// block 128x128, BK=16, 8 warps of 64x32.
template<int EPI>
__global__ __launch_bounds__(256)
void gemm_tf32_kernel(const float* __restrict__ A, const float* __restrict__ B,
                      const float* __restrict__ bias, const float* __restrict__ res,
                      float* __restrict__ C, int M, int N, int K)
{
    extern __shared__ float sm[];

    int tid  = threadIdx.x;
    int wid  = tid >> 5, lane = tid & 31;
    int g    = lane >> 2;
    int q    = lane & 3;
    int wm   = (wid >> 2) * 64;
    int wn   = (wid & 3) * 32;

    int row0 = blockIdx.y * 128;
    int col0 = blockIdx.x * 128;

    // cp.async chunk mapping (per thread, per stage): 2 A-chunks, 2 B-chunks of 16B
    int ar0 = tid >> 2;                 // 0..63  (A rows ar0, ar0+64)
    int ac0 = (tid & 3) << 2;           // col 0,4,8,12
    int br0 = tid >> 5;                 // 0..7   (B k-rows br0, br0+8)
    int bc0 = (tid & 31) << 2;          // col 0..124

    const float* Abase = A + (size_t)(row0 + ar0) * K + ac0;
    const float* Bbase = B + (size_t)br0 * N + col0 + bc0;

    float acc[4][4][4];
    #pragma unroll
    for (int mt = 0; mt < 4; mt++)
        #pragma unroll
        for (int nt = 0; nt < 4; nt++)
            #pragma unroll
            for (int r = 0; r < 4; r++) acc[mt][nt][r] = 0.f;

    const int KT = K >> 4;

    // prologue: stages 0..2
    #pragma unroll
    for (int st = 0; st < 3; st++) {
        float* as = sm + st * AS_TILE;
        float* bs = sm + GEMM_STAGES * AS_TILE + st * BS_TILE;
        int k0 = st * 16;
        cp16(as + ar0 * 20 + ac0,        Abase + k0);
        cp16(as + (ar0 + 64) * 20 + ac0, Abase + (size_t)64 * K + k0);
        cp16(bs + br0 * 136 + bc0,       Bbase + (size_t)k0 * N);
        cp16(bs + (br0 + 8) * 136 + bc0, Bbase + (size_t)(k0 + 8) * N);
        cp_commit();
    }

    for (int kt = 0; kt < KT; kt++) {
        cp_wait2();
        __syncthreads();

        if (kt + 3 < KT) {
            int st = (kt + 3) & 3;
            float* as = sm + st * AS_TILE;
            float* bs = sm + GEMM_STAGES * AS_TILE + st * BS_TILE;
            int k0 = (kt + 3) * 16;
            cp16(as + ar0 * 20 + ac0,        Abase + k0);
            cp16(as + (ar0 + 64) * 20 + ac0, Abase + (size_t)64 * K + k0);
            cp16(bs + br0 * 136 + bc0,       Bbase + (size_t)k0 * N);
            cp16(bs + (br0 + 8) * 136 + bc0, Bbase + (size_t)(k0 + 8) * N);
            cp_commit();
        }

        int st = kt & 3;
        const float* As = sm + st * AS_TILE;
        const float* Bs = sm + GEMM_STAGES * AS_TILE + st * BS_TILE;

        #pragma unroll
        for (int kk = 0; kk < 16; kk += 8) {
            unsigned af[4][4];
            #pragma unroll
            for (int mt = 0; mt < 4; mt++) {
                int r = wm + mt * 16 + g;
                af[mt][0] = __float_as_uint(As[r * 20 + kk + q]);
                af[mt][1] = __float_as_uint(As[(r + 8) * 20 + kk + q]);
                af[mt][2] = __float_as_uint(As[r * 20 + kk + 4 + q]);
                af[mt][3] = __float_as_uint(As[(r + 8) * 20 + kk + 4 + q]);
            }
            unsigned bf[4][2];
            #pragma unroll
            for (int nt = 0; nt < 4; nt++) {
                int c = wn + nt * 8 + g;
                bf[nt][0] = __float_as_uint(Bs[(kk + q) * 136 + c]);
                bf[nt][1] = __float_as_uint(Bs[(kk + 4 + q) * 136 + c]);
            }
            #pragma unroll
            for (int mt = 0; mt < 4; mt++)
                #pragma unroll
                for (int nt = 0; nt < 4; nt++) {
                    asm volatile(
                        "mma.sync.aligned.m16n8k8.row.col.f32.tf32.tf32.f32 "
                        "{%0,%1,%2,%3}, {%4,%5,%6,%7}, {%8,%9}, {%0,%1,%2,%3};"
                        : "+f"(acc[mt][nt][0]), "+f"(acc[mt][nt][1]),
                          "+f"(acc[mt][nt][2]), "+f"(acc[mt][nt][3])
                        : "r"(af[mt][0]), "r"(af[mt][1]), "r"(af[mt][2]), "r"(af[mt][3]),
                          "r"(bf[nt][0]), "r"(bf[nt][1]));
                }
        }
    }

    #pragma unroll
    for (int mt = 0; mt < 4; mt++) {
        int r = row0 + wm + mt * 16 + g;
        #pragma unroll
        for (int nt = 0; nt < 4; nt++) {
            int c = col0 + wn + nt * 8 + 2 * q;
            float bv0 = bias[c], bv1 = bias[c + 1];
            float v00 = acc[mt][nt][0] + bv0;
            float v01 = acc[mt][nt][1] + bv1;
            float v10 = acc[mt][nt][2] + bv0;
            float v11 = acc[mt][nt][3] + bv1;
            if (EPI == 1) {
                v00 = tf32r(0.5f * v00 * (1.0f + erff(v00 * 0.70710678118654752f)));
                v01 = tf32r(0.5f * v01 * (1.0f + erff(v01 * 0.70710678118654752f)));
                v10 = tf32r(0.5f * v10 * (1.0f + erff(v10 * 0.70710678118654752f)));
                v11 = tf32r(0.5f * v11 * (1.0f + erff(v11 * 0.70710678118654752f)));
            }
            if (EPI == 2) {
                float2 r0 = *(const float2*)(res + (size_t)r * N + c);
                float2 r1 = *(const float2*)(res + (size_t)(r + 8) * N + c);
                v00 += r0.x; v01 += r0.y;
                v10 += r1.x; v11 += r1.y;
            }
            *(float2*)(C + (size_t)r * N + c)       = make_float2(v00, v01);
            *(float2*)(C + (size_t)(r + 8) * N + c) = make_float2(v10, v11);
        }
    }
}

// ---------------- TF32 tensor-core flash attention (output tf32-rounded) ----------------
__global__ __launch_bounds__(128)
void attn_tc_kernel(const float* __restrict__ Q, const float* __restrict__ K,
                    const float* __restrict__ V, float* __restrict__ O)
{
    extern __shared__ float sm[];
    float* Qs = sm;
    float* Ks = sm + 64 * QS_STRIDE;
    float* Vs = sm + 64 * (QS_STRIDE + KS_STRIDE);

    int tid  = threadIdx.x;
    int wid  = tid >> 5, lane = tid & 31;
    int g    = lane >> 2;
    int q    = lane & 3;
    int qt   = blockIdx.x;
    int bh   = blockIdx.y;
    int b    = bh >> 4;
    int h    = bh & 15;
    int kvh  = h >> 2;
    int q0   = qt * 64;

    const float* Qb = Q + (size_t)(b * NHEAD + h)  * S_LEN * 64 + (size_t)q0 * 64;
    const float* Kb = K + (size_t)(b * NKV  + kvh) * S_LEN * 64;
    const float* Vb = V + (size_t)(b * NKV  + kvh) * S_LEN * 64;

    for (int i = tid; i < 64 * 16; i += 128) {
        int r = i >> 4, c = (i & 15) << 2;
        float4 v = *(const float4*)(Qb + (size_t)r * 64 + c);
        *(float4*)&Qs[r * QS_STRIDE + c] = make_float4(tf32r(v.x), tf32r(v.y),
                                                       tf32r(v.z), tf32r(v.w));
    }

    float m0 = -INFINITY, m1 = -INFINITY, l0 = 0.f, l1 = 0.f;
    float o[8][4];
    #pragma unroll
    for (int nt = 0; nt < 8; nt++)
        #pragma unroll
        for (int r = 0; r < 4; r++) o[nt][r] = 0.f;

    int row_a = 16 * wid + g;
    int nkt = qt + 1;

    for (int jt = 0; jt < nkt; ++jt) {
        int j0 = jt * 64;
        __syncthreads();
        for (int i = tid; i < 64 * 16; i += 128) {
            int r = i >> 4, c = (i & 15) << 2;
            float4 kv = *(const float4*)(Kb + (size_t)(j0 + r) * 64 + c);
            *(float4*)&Ks[r * KS_STRIDE + c] = make_float4(tf32r(kv.x), tf32r(kv.y),
                                                           tf32r(kv.z), tf32r(kv.w));
            float4 vv = *(const float4*)(Vb + (size_t)(j0 + r) * 64 + c);
            *(float4*)&Vs[r * VS_STRIDE + c] = make_float4(tf32r(vv.x), tf32r(vv.y),
                                                           tf32r(vv.z), tf32r(vv.w));
        }
        __syncthreads();

        float s[8][4];
        #pragma unroll
        for (int nt = 0; nt < 8; nt++)
            #pragma unroll
            for (int r = 0; r < 4; r++) s[nt][r] = 0.f;

        #pragma unroll
        for (int k0 = 0; k0 < 64; k0 += 8) {
            unsigned a0 = __float_as_uint(Qs[(row_a)     * QS_STRIDE + k0 + q]);
            unsigned a1 = __float_as_uint(Qs[(row_a + 8) * QS_STRIDE + k0 + q]);
            unsigned a2 = __float_as_uint(Qs[(row_a)     * QS_STRIDE + k0 + q + 4]);
            unsigned a3 = __float_as_uint(Qs[(row_a + 8) * QS_STRIDE + k0 + q + 4]);
            #pragma unroll
            for (int nt = 0; nt < 8; nt++) {
                unsigned b0 = __float_as_uint(Ks[(nt * 8 + g) * KS_STRIDE + k0 + q]);
                unsigned b1 = __float_as_uint(Ks[(nt * 8 + g) * KS_STRIDE + k0 + q + 4]);
                asm volatile(
                    "mma.sync.aligned.m16n8k8.row.col.f32.tf32.tf32.f32 "
                    "{%0,%1,%2,%3}, {%4,%5,%6,%7}, {%8,%9}, {%0,%1,%2,%3};"
                    : "+f"(s[nt][0]), "+f"(s[nt][1]), "+f"(s[nt][2]), "+f"(s[nt][3])
                    : "r"(a0), "r"(a1), "r"(a2), "r"(a3), "r"(b0), "r"(b1));
            }
        }

        if (jt == qt) {
            #pragma unroll
            for (int nt = 0; nt < 8; nt++) {
                int col = nt * 8 + 2 * q;
                if (col     > row_a)     s[nt][0] = -INFINITY;
                if (col + 1 > row_a)     s[nt][1] = -INFINITY;
                if (col     > row_a + 8) s[nt][2] = -INFINITY;
                if (col + 1 > row_a + 8) s[nt][3] = -INFINITY;
            }
        }

        float mt0 = -INFINITY, mt1 = -INFINITY;
        #pragma unroll
        for (int nt = 0; nt < 8; nt++) {
            mt0 = fmaxf(mt0, fmaxf(s[nt][0], s[nt][1]));
            mt1 = fmaxf(mt1, fmaxf(s[nt][2], s[nt][3]));
        }
        #pragma unroll
        for (int off = 1; off < 4; off <<= 1) {
            mt0 = fmaxf(mt0, __shfl_xor_sync(0xffffffffu, mt0, off));
            mt1 = fmaxf(mt1, __shfl_xor_sync(0xffffffffu, mt1, off));
        }
        float mn0 = fmaxf(m0, mt0), mn1 = fmaxf(m1, mt1);
        float al0 = __expf(m0 - mn0), al1 = __expf(m1 - mn1);
        m0 = mn0; m1 = mn1;
        float ps0 = 0.f, ps1 = 0.f;
        #pragma unroll
        for (int nt = 0; nt < 8; nt++) {
            s[nt][0] = __expf(s[nt][0] - mn0);
            s[nt][1] = __expf(s[nt][1] - mn0);
            s[nt][2] = __expf(s[nt][2] - mn1);
            s[nt][3] = __expf(s[nt][3] - mn1);
            ps0 += s[nt][0] + s[nt][1];
            ps1 += s[nt][2] + s[nt][3];
            o[nt][0] *= al0; o[nt][1] *= al0;
            o[nt][2] *= al1; o[nt][3] *= al1;
        }
        #pragma unroll
        for (int off = 1; off < 4; off <<= 1) {
            ps0 += __shfl_xor_sync(0xffffffffu, ps0, off);
            ps1 += __shfl_xor_sync(0xffffffffu, ps1, off);
        }
        l0 = l0 * al0 + ps0;
        l1 = l1 * al1 + ps1;

        int base  = lane & ~3;
        int srcLo = base + (q >> 1);
        int srcHi = base + 2 + (q >> 1);
        bool odd  = q & 1;
        #pragma unroll
        for (int kc = 0; kc < 8; kc++) {
            float p0 = s[kc][0], p1 = s[kc][1], p2 = s[kc][2], p3 = s[kc][3];
            float t0 = __shfl_sync(0xffffffffu, p0, srcLo);
            float t1 = __shfl_sync(0xffffffffu, p1, srcLo);
            float t2 = __shfl_sync(0xffffffffu, p2, srcLo);
            float t3 = __shfl_sync(0xffffffffu, p3, srcLo);
            float u0 = __shfl_sync(0xffffffffu, p0, srcHi);
            float u1 = __shfl_sync(0xffffffffu, p1, srcHi);
            float u2 = __shfl_sync(0xffffffffu, p2, srcHi);
            float u3 = __shfl_sync(0xffffffffu, p3, srcHi);
            unsigned a0 = f2tf32(odd ? t1 : t0);
            unsigned a1 = f2tf32(odd ? t3 : t2);
            unsigned a2 = f2tf32(odd ? u1 : u0);
            unsigned a3 = f2tf32(odd ? u3 : u2);
            #pragma unroll
            for (int nt = 0; nt < 8; nt++) {
                unsigned b0 = __float_as_uint(Vs[(kc * 8 + q)     * VS_STRIDE + nt * 8 + g]);
                unsigned b1 = __float_as_uint(Vs[(kc * 8 + q + 4) * VS_STRIDE + nt * 8 + g]);
                asm volatile(
                    "mma.sync.aligned.m16n8k8.row.col.f32.tf32.tf32.f32 "
                    "{%0,%1,%2,%3}, {%4,%5,%6,%7}, {%8,%9}, {%0,%1,%2,%3};"
                    : "+f"(o[nt][0]), "+f"(o[nt][1]), "+f"(o[nt][2]), "+f"(o[nt][3])
                    : "r"(a0), "r"(a1), "r"(a2), "r"(a3), "r"(b0), "r"(b1));
            }
        }
    }

    float inv0 = 1.0f / l0, inv1 = 1.0f / l1;
    int srow0 = q0 + row_a;
    int srow1 = srow0 + 8;
    #pragma unroll
    for (int nt = 0; nt < 8; nt++) {
        int c = h * 64 + nt * 8 + 2 * q;
        *(float2*)(O + ((size_t)srow0 * BATCH + b) * DMODEL + c) =
            make_float2(tf32r(o[nt][0] * inv0), tf32r(o[nt][1] * inv0));
        *(float2*)(O + ((size_t)srow1 * BATCH + b) * DMODEL + c) =
            make_float2(tf32r(o[nt][2] * inv1), tf32r(o[nt][3] * inv1));
    }
}

// ---------------- host orchestration ----------------
extern "C" void kernel_launch(void* const* d_in, const int* in_sizes, int n_in,
                              void* d_out, int out_size)
{
    const float* x   = (const float*)d_in[0];
    const float* n1w = (const float*)d_in[1];
    const float* wq  = (const float*)d_in[2];
    const float* bq  = (const float*)d_in[3];
    const float* wk  = (const float*)d_in[4];
    const float* bk  = (const float*)d_in[5];
    const float* wv  = (const float*)d_in[6];
    const float* bv  = (const float*)d_in[7];
    const float* qnw = (const float*)d_in[8];
    const float* knw = (const float*)d_in[9];
    const float* wo  = (const float*)d_in[10];
    const float* bo  = (const float*)d_in[11];
    const float* n2w = (const float*)d_in[12];
    const float* w1  = (const float*)d_in[13];
    const float* b1  = (const float*)d_in[14];
    const float* w2  = (const float*)d_in[15];
    const float* b2  = (const float*)d_in[16];

    float *ph, *pwqkv, *pbqkv, *pqkv, *pq, *pk, *pv, *pattn, *px1, *ph2, *pmid;
    float *pwor, *pw1r, *pw2r;
    cudaGetSymbolAddress((void**)&ph,    g_h);
    cudaGetSymbolAddress((void**)&pwqkv, g_wqkv);
    cudaGetSymbolAddress((void**)&pbqkv, g_bqkv);
    cudaGetSymbolAddress((void**)&pqkv,  g_qkv);
    cudaGetSymbolAddress((void**)&pq,    g_q);
    cudaGetSymbolAddress((void**)&pk,    g_k);
    cudaGetSymbolAddress((void**)&pv,    g_v);
    cudaGetSymbolAddress((void**)&pattn, g_attn);
    cudaGetSymbolAddress((void**)&px1,   g_x1);
    cudaGetSymbolAddress((void**)&ph2,   g_h2);
    cudaGetSymbolAddress((void**)&pmid,  g_mid);
    cudaGetSymbolAddress((void**)&pwor,  g_wor);
    cudaGetSymbolAddress((void**)&pw1r,  g_w1r);
    cudaGetSymbolAddress((void**)&pw2r,  g_w2r);

    cudaFuncSetAttribute(attn_tc_kernel,
                         cudaFuncAttributeMaxDynamicSharedMemorySize, ATTN_SMEM_BYTES);
    cudaFuncSetAttribute(gemm_tf32_kernel<0>,
                         cudaFuncAttributeMaxDynamicSharedMemorySize, GEMM_SMEM_BYTES);
    cudaFuncSetAttribute(gemm_tf32_kernel<1>,
                         cudaFuncAttributeMaxDynamicSharedMemorySize, GEMM_SMEM_BYTES);
    cudaFuncSetAttribute(gemm_tf32_kernel<2>,
                         cudaFuncAttributeMaxDynamicSharedMemorySize, GEMM_SMEM_BYTES);

    pack_wqkv_kernel<<<(DMODEL * QKVN + 255) / 256, 256>>>(wq, wk, wv, bq, bk, bv, pwqkv, pbqkv);
    roundcopy_kernel<<<(DMODEL * DMODEL / 4 + 255) / 256, 256>>>(wo, pwor, DMODEL * DMODEL / 4);
    roundcopy_kernel<<<(DMODEL * DFF / 4 + 255) / 256, 256>>>(w1, pw1r, DMODEL * DFF / 4);
    roundcopy_kernel<<<(DFF * DMODEL / 4 + 255) / 256, 256>>>(w2, pw2r, DFF * DMODEL / 4);
    rmsnorm_kernel<<<NTOK, 256>>>(x, n1w, ph);
    gemm_tf32_kernel<0><<<dim3(QKVN / 128, NTOK / 128), 256, GEMM_SMEM_BYTES>>>(
        ph, pwqkv, pbqkv, nullptr, pqkv, NTOK, QKVN, DMODEL);
    qkrope_kernel<<<dim3(NTOK, 6), dim3(64, 4)>>>(pqkv, qnw, knw, pq, pk, pv);
    attn_tc_kernel<<<dim3(S_LEN / 64, BATCH * NHEAD), 128, ATTN_SMEM_BYTES>>>(pq, pk, pv, pattn);
    gemm_tf32_kernel<2><<<dim3(DMODEL / 128, NTOK / 128), 256, GEMM_SMEM_BYTES>>>(
        pattn, pwor, bo, x, px1, NTOK, DMODEL, DMODEL);
    rmsnorm_kernel<<<NTOK, 256>>>(px1, n2w, ph2);
    gemm_tf32_kernel<1><<<dim3(DFF / 128, NTOK / 128), 256, GEMM_SMEM_BYTES>>>(
        ph2, pw1r, b1, nullptr, pmid, NTOK, DFF, DMODEL);
    gemm_tf32_kernel<2><<<dim3(DMODEL / 128, NTOK / 128), 256, GEMM_SMEM_BYTES>>>(
        pmid, pw2r, b2, px1, (float*)d_out, NTOK, DMODEL, DFF);
}

// round 8
// speedup vs baseline: 3.2669x; 1.0182x over previous
#include <cuda_runtime.h>
#include <math.h>

#define S_LEN   2048
#define BATCH   2
#define DMODEL  1024
#define NHEAD   16
#define NKV     4
#define HEADDIM 64
#define NTOK    4096            // S_LEN * BATCH
#define DFF     4096            // 4 * DMODEL
#define QKVN    1536            // 1024 + 256 + 256
#define EPS_F   1e-5f
#define QK_SCALE 0.03125f       // D^-0.5 = 1/32

// attention smem layout (floats)
#define QS_STRIDE 68
#define KS_STRIDE 68
#define VS_STRIDE 72
#define ATTN_SMEM_FLOATS (64*QS_STRIDE + 64*KS_STRIDE + 64*VS_STRIDE)
#define ATTN_SMEM_BYTES  (ATTN_SMEM_FLOATS * 4)

// GEMM smem: 4 stages, A tile 128x16 stored [m][20], B tile 16x128 stored [k][136]
#define AS_TILE 2560            // 128*20 floats
#define BS_TILE 2176            // 16*136 floats
#define GEMM_STAGES 4
#define GEMM_SMEM_FLOATS (GEMM_STAGES * (AS_TILE + BS_TILE))
#define GEMM_SMEM_BYTES  (GEMM_SMEM_FLOATS * 4)

// ---------------- scratch (__device__ globals; no allocation allowed) ----------------
__device__ float g_h   [NTOK * DMODEL];
__device__ float g_wqkv[DMODEL * QKVN];
__device__ float g_bqkv[QKVN];
__device__ float g_qkv [NTOK * QKVN];
__device__ float g_q   [BATCH * NHEAD * S_LEN * HEADDIM];
__device__ float g_k   [BATCH * NKV   * S_LEN * HEADDIM];
__device__ float g_v   [BATCH * NKV   * S_LEN * HEADDIM];
__device__ float g_attn[NTOK * DMODEL];
__device__ float g_x1  [NTOK * DMODEL];
__device__ float g_h2  [NTOK * DMODEL];
__device__ float g_mid [NTOK * DFF];
__device__ float g_wor [DMODEL * DMODEL];
__device__ float g_w1r [DMODEL * DFF];
__device__ float g_w2r [DFF * DMODEL];

__device__ __forceinline__ unsigned f2tf32(float x) {
    unsigned u;
    asm("cvt.rna.tf32.f32 %0, %1;" : "=r"(u) : "f"(x));
    return u;
}
__device__ __forceinline__ float tf32r(float x) { return __uint_as_float(f2tf32(x)); }

__device__ __forceinline__ void cp16(float* dst_smem, const float* src) {
    unsigned d = (unsigned)__cvta_generic_to_shared(dst_smem);
    asm volatile("cp.async.ca.shared.global [%0], [%1], 16;" :: "r"(d), "l"(src));
}
__device__ __forceinline__ void cp_commit() {
    asm volatile("cp.async.commit_group;" ::: "memory");
}
__device__ __forceinline__ void cp_wait2() {
    asm volatile("cp.async.wait_group 2;" ::: "memory");
}

// ---------------- round-to-tf32 copy (for wo, w1, w2) ----------------
__global__ __launch_bounds__(256)
void roundcopy_kernel(const float* __restrict__ src, float* __restrict__ dst, int n4)
{
    int i = blockIdx.x * 256 + threadIdx.x;
    if (i < n4) {
        float4 v = ((const float4*)src)[i];
        ((float4*)dst)[i] = make_float4(tf32r(v.x), tf32r(v.y), tf32r(v.z), tf32r(v.w));
    }
}

// ---------------- pack wq|wk|wv into one [D, 1536] weight (tf32-rounded) ----------------
__global__ void pack_wqkv_kernel(const float* __restrict__ wq, const float* __restrict__ wk,
                                 const float* __restrict__ wv, const float* __restrict__ bq,
                                 const float* __restrict__ bk, const float* __restrict__ bv,
                                 float* __restrict__ W, float* __restrict__ bias)
{
    int idx = blockIdx.x * 256 + threadIdx.x;
    if (idx < DMODEL * QKVN) {
        int k = idx / QKVN, c = idx % QKVN;
        float v;
        if (c < 1024)       v = wq[k * 1024 + c];
        else if (c < 1280)  v = wk[k * 256 + (c - 1024)];
        else                v = wv[k * 256 + (c - 1280)];
        W[idx] = tf32r(v);
    }
    if (idx < QKVN) {
        bias[idx] = (idx < 1024) ? bq[idx] : (idx < 1280 ? bk[idx - 1024] : bv[idx - 1280]);
    }
}

// ---------------- RMSNorm over D=1024 (output tf32-rounded; feeds GEMM A) ----------------
__global__ __launch_bounds__(256)
void rmsnorm_kernel(const float* __restrict__ x, const float* __restrict__ w,
                    float* __restrict__ y)
{
    int row = blockIdx.x;
    int i = threadIdx.x;
    const float* xr = x + (size_t)row * DMODEL;
    float4 xv = *(const float4*)(xr + i * 4);
    float ss = xv.x * xv.x + xv.y * xv.y + xv.z * xv.z + xv.w * xv.w;
    #pragma unroll
    for (int off = 16; off; off >>= 1) ss += __shfl_xor_sync(0xffffffffu, ss, off);
    __shared__ float red[8];
    __shared__ float s_sc;
    if ((i & 31) == 0) red[i >> 5] = ss;
    __syncthreads();
    if (i == 0) {
        float tot = 0.f;
        #pragma unroll
        for (int kk = 0; kk < 8; kk++) tot += red[kk];
        s_sc = rsqrtf(tot * (1.0f / DMODEL) + EPS_F);
    }
    __syncthreads();
    float sc = s_sc;
    float4 wv = *(const float4*)(w + i * 4);
    float4 ov = make_float4(tf32r(xv.x * sc * wv.x), tf32r(xv.y * sc * wv.y),
                            tf32r(xv.z * sc * wv.z), tf32r(xv.w * sc * wv.w));
    *(float4*)(y + (size_t)row * DMODEL + i * 4) = ov;
}

// ---------------- per-head QK RMSNorm + RoPE + relayout; V relayout ----------------
__global__ __launch_bounds__(256)
void qkrope_kernel(const float* __restrict__ qkv, const float* __restrict__ qn_w,
                   const float* __restrict__ kn_w, float* __restrict__ Qo,
                   float* __restrict__ Ko, float* __restrict__ Vo)
{
    int t = blockIdx.x;            // token = s*BATCH + b
    int ty = threadIdx.y;          // 0..3
    int slot = blockIdx.y * 4 + ty;
    int i = threadIdx.x;           // 0..63
    int s = t / BATCH, b = t % BATCH;
    __shared__ float buf[4][64];
    __shared__ float red[4][2];

    if (slot >= 20) {   // V: pure relayout (whole block is V)
        int vh = slot - 20;
        float v = qkv[(size_t)t * QKVN + 1280 + vh * 64 + i];
        Vo[((size_t)(b * NKV + vh) * S_LEN + s) * 64 + i] = v;
        return;
    }

    bool is_q = (slot < 16);
    int col = is_q ? (slot * 64 + i) : (1024 + (slot - 16) * 64 + i);
    float v = qkv[(size_t)t * QKVN + col];
    float ss = v * v;
    #pragma unroll
    for (int off = 16; off; off >>= 1) ss += __shfl_xor_sync(0xffffffffu, ss, off);
    if ((i & 31) == 0) red[ty][i >> 5] = ss;
    __syncthreads();
    float tot = red[ty][0] + red[ty][1];
    float sc = rsqrtf(tot * (1.0f / 64.0f) + EPS_F);
    const float* w = is_q ? qn_w : kn_w;
    float nv = v * sc * w[i];
    buf[ty][i] = nv;
    __syncthreads();
    float rot = (i < 32) ? -buf[ty][i + 32] : buf[ty][i - 32];
    int j = i & 31;
    float invf = exp2f(-(float)j * (13.287712379549449f / 32.0f));
    float ang = (float)s * invf;
    float sn, cs;
    sincosf(ang, &sn, &cs);
    float outv = nv * cs + rot * sn;
    if (is_q) {
        outv *= QK_SCALE;
        Qo[((size_t)(b * NHEAD + slot) * S_LEN + s) * 64 + i] = outv;
    } else {
        Ko[((size_t)(b * NKV + (slot - 16)) * S_LEN + s) * 64 + i] = outv;
    }
}

// ---------------- GEMM stage loader: 8 cp.async per thread (128 threads) ----------------
__device__ __forceinline__ void gemm_stage_load(float* as, float* bs,
                                                const float* Abase, const float* Bbase,
                                                int k0, int K, int N,
                                                int ar0, int ac0, int br0, int bc0)
{
    #pragma unroll
    for (int j = 0; j < 4; j++)
        cp16(as + (ar0 + 32 * j) * 20 + ac0, Abase + (size_t)(32 * j) * K + k0);
    #pragma unroll
    for (int j = 0; j < 4; j++)
        cp16(bs + (br0 + 4 * j) * 136 + bc0, Bbase + (size_t)(k0 + 4 * j) * N);
}

// ---------------- TF32 GEMM, 4-stage cp.async, 4 warps of 64x64 ----------------
// A and B MUST already be tf32-rounded (raw bits copied to smem).
// EPI: 0 = +bias, 1 = gelu(+bias) tf32-rounded out, 2 = +bias + residual
// block 128x128, BK=16, warp grid 2x2, warp tile 64x64 (1 LDS per mma).
template<int EPI>
__global__ __launch_bounds__(128)
void gemm_tf32_kernel(const float* __restrict__ A, const float* __restrict__ B,
                      const float* __restrict__ bias, const float* __restrict__ res,
                      float* __restrict__ C, int M, int N, int K)
{
    extern __shared__ float sm[];

    int tid  = threadIdx.x;
    int wid  = tid >> 5, lane = tid & 31;
    int g    = lane >> 2;
    int q    = lane & 3;
    int wm   = (wid >> 1) * 64;        // 0 / 64
    int wn   = (wid & 1) * 64;         // 0 / 64

    int row0 = blockIdx.y * 128;
    int col0 = blockIdx.x * 128;

    // cp.async mapping (128 threads): A rows ar0+32j, B k-rows br0+4j
    int ar0 = tid >> 2;                 // 0..31
    int ac0 = (tid & 3) << 2;           // 0,4,8,12
    int br0 = tid >> 5;                 // 0..3
    int bc0 = (tid & 31) << 2;          // 0..124

    const float* Abase = A + (size_t)(row0 + ar0) * K + ac0;
    const float* Bbase = B + (size_t)br0 * N + col0 + bc0;

    float acc[4][8][4];
    #pragma unroll
    for (int mt = 0; mt < 4; mt++)
        #pragma unroll
        for (int nt = 0; nt < 8; nt++)
            #pragma unroll
            for (int r = 0; r < 4; r++) acc[mt][nt][r] = 0.f;

    const int KT = K >> 4;

    // prologue: stages 0..2
    #pragma unroll
    for (int st = 0; st < 3; st++) {
        gemm_stage_load(sm + st * AS_TILE, sm + GEMM_STAGES * AS_TILE + st * BS_TILE,
                        Abase, Bbase, st * 16, K, N, ar0, ac0, br0, bc0);
        cp_commit();
    }

    for (int kt = 0; kt < KT; kt++) {
        cp_wait2();
        __syncthreads();

        if (kt + 3 < KT) {
            int st = (kt + 3) & 3;
            gemm_stage_load(sm + st * AS_TILE, sm + GEMM_STAGES * AS_TILE + st * BS_TILE,
                            Abase, Bbase, (kt + 3) * 16, K, N, ar0, ac0, br0, bc0);
            cp_commit();
        }

        int st = kt & 3;
        const float* As = sm + st * AS_TILE;
        const float* Bs = sm + GEMM_STAGES * AS_TILE + st * BS_TILE;

        #pragma unroll
        for (int kk = 0; kk < 16; kk += 8) {
            unsigned af[4][4];
            #pragma unroll
            for (int mt = 0; mt < 4; mt++) {
                int r = wm + mt * 16 + g;
                af[mt][0] = __float_as_uint(As[r * 20 + kk + q]);
                af[mt][1] = __float_as_uint(As[(r + 8) * 20 + kk + q]);
                af[mt][2] = __float_as_uint(As[r * 20 + kk + 4 + q]);
                af[mt][3] = __float_as_uint(As[(r + 8) * 20 + kk + 4 + q]);
            }
            unsigned bf[8][2];
            #pragma unroll
            for (int nt = 0; nt < 8; nt++) {
                int c = wn + nt * 8 + g;
                bf[nt][0] = __float_as_uint(Bs[(kk + q) * 136 + c]);
                bf[nt][1] = __float_as_uint(Bs[(kk + 4 + q) * 136 + c]);
            }
            #pragma unroll
            for (int mt = 0; mt < 4; mt++)
                #pragma unroll
                for (int nt = 0; nt < 8; nt++) {
                    asm volatile(
                        "mma.sync.aligned.m16n8k8.row.col.f32.tf32.tf32.f32 "
                        "{%0,%1,%2,%3}, {%4,%5,%6,%7}, {%8,%9}, {%0,%1,%2,%3};"
                        : "+f"(acc[mt][nt][0]), "+f"(acc[mt][nt][1]),
                          "+f"(acc[mt][nt][2]), "+f"(acc[mt][nt][3])
                        : "r"(af[mt][0]), "r"(af[mt][1]), "r"(af[mt][2]), "r"(af[mt][3]),
                          "r"(bf[nt][0]), "r"(bf[nt][1]));
                }
        }
    }

    #pragma unroll
    for (int mt = 0; mt < 4; mt++) {
        int r = row0 + wm + mt * 16 + g;
        #pragma unroll
        for (int nt = 0; nt < 8; nt++) {
            int c = col0 + wn + nt * 8 + 2 * q;
            float bv0 = bias[c], bv1 = bias[c + 1];
            float v00 = acc[mt][nt][0] + bv0;
            float v01 = acc[mt][nt][1] + bv1;
            float v10 = acc[mt][nt][2] + bv0;
            float v11 = acc[mt][nt][3] + bv1;
            if (EPI == 1) {
                v00 = tf32r(0.5f * v00 * (1.0f + erff(v00 * 0.70710678118654752f)));
                v01 = tf32r(0.5f * v01 * (1.0f + erff(v01 * 0.70710678118654752f)));
                v10 = tf32r(0.5f * v10 * (1.0f + erff(v10 * 0.70710678118654752f)));
                v11 = tf32r(0.5f * v11 * (1.0f + erff(v11 * 0.70710678118654752f)));
            }
            if (EPI == 2) {
                float2 r0 = *(const float2*)(res + (size_t)r * N + c);
                float2 r1 = *(const float2*)(res + (size_t)(r + 8) * N + c);
                v00 += r0.x; v01 += r0.y;
                v10 += r1.x; v11 += r1.y;
            }
            *(float2*)(C + (size_t)r * N + c)       = make_float2(v00, v01);
            *(float2*)(C + (size_t)(r + 8) * N + c) = make_float2(v10, v11);
        }
    }
}

// ---------------- TF32 tensor-core flash attention (unchanged) ----------------
__global__ __launch_bounds__(128)
void attn_tc_kernel(const float* __restrict__ Q, const float* __restrict__ K,
                    const float* __restrict__ V, float* __restrict__ O)
{
    extern __shared__ float sm[];
    float* Qs = sm;
    float* Ks = sm + 64 * QS_STRIDE;
    float* Vs = sm + 64 * (QS_STRIDE + KS_STRIDE);

    int tid  = threadIdx.x;
    int wid  = tid >> 5, lane = tid & 31;
    int g    = lane >> 2;
    int q    = lane & 3;
    int qt   = blockIdx.x;
    int bh   = blockIdx.y;
    int b    = bh >> 4;
    int h    = bh & 15;
    int kvh  = h >> 2;
    int q0   = qt * 64;

    const float* Qb = Q + (size_t)(b * NHEAD + h)  * S_LEN * 64 + (size_t)q0 * 64;
    const float* Kb = K + (size_t)(b * NKV  + kvh) * S_LEN * 64;
    const float* Vb = V + (size_t)(b * NKV  + kvh) * S_LEN * 64;

    for (int i = tid; i < 64 * 16; i += 128) {
        int r = i >> 4, c = (i & 15) << 2;
        float4 v = *(const float4*)(Qb + (size_t)r * 64 + c);
        *(float4*)&Qs[r * QS_STRIDE + c] = make_float4(tf32r(v.x), tf32r(v.y),
                                                       tf32r(v.z), tf32r(v.w));
    }

    float m0 = -INFINITY, m1 = -INFINITY, l0 = 0.f, l1 = 0.f;
    float o[8][4];
    #pragma unroll
    for (int nt = 0; nt < 8; nt++)
        #pragma unroll
        for (int r = 0; r < 4; r++) o[nt][r] = 0.f;

    int row_a = 16 * wid + g;
    int nkt = qt + 1;

    for (int jt = 0; jt < nkt; ++jt) {
        int j0 = jt * 64;
        __syncthreads();
        for (int i = tid; i < 64 * 16; i += 128) {
            int r = i >> 4, c = (i & 15) << 2;
            float4 kv = *(const float4*)(Kb + (size_t)(j0 + r) * 64 + c);
            *(float4*)&Ks[r * KS_STRIDE + c] = make_float4(tf32r(kv.x), tf32r(kv.y),
                                                           tf32r(kv.z), tf32r(kv.w));
            float4 vv = *(const float4*)(Vb + (size_t)(j0 + r) * 64 + c);
            *(float4*)&Vs[r * VS_STRIDE + c] = make_float4(tf32r(vv.x), tf32r(vv.y),
                                                           tf32r(vv.z), tf32r(vv.w));
        }
        __syncthreads();

        float s[8][4];
        #pragma unroll
        for (int nt = 0; nt < 8; nt++)
            #pragma unroll
            for (int r = 0; r < 4; r++) s[nt][r] = 0.f;

        #pragma unroll
        for (int k0 = 0; k0 < 64; k0 += 8) {
            unsigned a0 = __float_as_uint(Qs[(row_a)     * QS_STRIDE + k0 + q]);
            unsigned a1 = __float_as_uint(Qs[(row_a + 8) * QS_STRIDE + k0 + q]);
            unsigned a2 = __float_as_uint(Qs[(row_a)     * QS_STRIDE + k0 + q + 4]);
            unsigned a3 = __float_as_uint(Qs[(row_a + 8) * QS_STRIDE + k0 + q + 4]);
            #pragma unroll
            for (int nt = 0; nt < 8; nt++) {
                unsigned b0 = __float_as_uint(Ks[(nt * 8 + g) * KS_STRIDE + k0 + q]);
                unsigned b1 = __float_as_uint(Ks[(nt * 8 + g) * KS_STRIDE + k0 + q + 4]);
                asm volatile(
                    "mma.sync.aligned.m16n8k8.row.col.f32.tf32.tf32.f32 "
                    "{%0,%1,%2,%3}, {%4,%5,%6,%7}, {%8,%9}, {%0,%1,%2,%3};"
                    : "+f"(s[nt][0]), "+f"(s[nt][1]), "+f"(s[nt][2]), "+f"(s[nt][3])
                    : "r"(a0), "r"(a1), "r"(a2), "r"(a3), "r"(b0), "r"(b1));
            }
        }

        if (jt == qt) {
            #pragma unroll
            for (int nt = 0; nt < 8; nt++) {
                int col = nt * 8 + 2 * q;
                if (col     > row_a)     s[nt][0] = -INFINITY;
                if (col + 1 > row_a)     s[nt][1] = -INFINITY;
                if (col     > row_a + 8) s[nt][2] = -INFINITY;
                if (col + 1 > row_a + 8) s[nt][3] = -INFINITY;
            }
        }

        float mt0 = -INFINITY, mt1 = -INFINITY;
        #pragma unroll
        for (int nt = 0; nt < 8; nt++) {
            mt0 = fmaxf(mt0, fmaxf(s[nt][0], s[nt][1]));
            mt1 = fmaxf(mt1, fmaxf(s[nt][2], s[nt][3]));
        }
        #pragma unroll
        for (int off = 1; off < 4; off <<= 1) {
            mt0 = fmaxf(mt0, __shfl_xor_sync(0xffffffffu, mt0, off));
            mt1 = fmaxf(mt1, __shfl_xor_sync(0xffffffffu, mt1, off));
        }
        float mn0 = fmaxf(m0, mt0), mn1 = fmaxf(m1, mt1);
        float al0 = __expf(m0 - mn0), al1 = __expf(m1 - mn1);
        m0 = mn0; m1 = mn1;
        float ps0 = 0.f, ps1 = 0.f;
        #pragma unroll
        for (int nt = 0; nt < 8; nt++) {
            s[nt][0] = __expf(s[nt][0] - mn0);
            s[nt][1] = __expf(s[nt][1] - mn0);
            s[nt][2] = __expf(s[nt][2] - mn1);
            s[nt][3] = __expf(s[nt][3] - mn1);
            ps0 += s[nt][0] + s[nt][1];
            ps1 += s[nt][2] + s[nt][3];
            o[nt][0] *= al0; o[nt][1] *= al0;
            o[nt][2] *= al1; o[nt][3] *= al1;
        }
        #pragma unroll
        for (int off = 1; off < 4; off <<= 1) {
            ps0 += __shfl_xor_sync(0xffffffffu, ps0, off);
            ps1 += __shfl_xor_sync(0xffffffffu, ps1, off);
        }
        l0 = l0 * al0 + ps0;
        l1 = l1 * al1 + ps1;

        int base  = lane & ~3;
        int srcLo = base + (q >> 1);
        int srcHi = base + 2 + (q >> 1);
        bool odd  = q & 1;
        #pragma unroll
        for (int kc = 0; kc < 8; kc++) {
            float p0 = s[kc][0], p1 = s[kc][1], p2 = s[kc][2], p3 = s[kc][3];
            float t0 = __shfl_sync(0xffffffffu, p0, srcLo);
            float t1 = __shfl_sync(0xffffffffu, p1, srcLo);
            float t2 = __shfl_sync(0xffffffffu, p2, srcLo);
            float t3 = __shfl_sync(0xffffffffu, p3, srcLo);
            float u0 = __shfl_sync(0xffffffffu, p0, srcHi);
            float u1 = __shfl_sync(0xffffffffu, p1, srcHi);
            float u2 = __shfl_sync(0xffffffffu, p2, srcHi);
            float u3 = __shfl_sync(0xffffffffu, p3, srcHi);
            unsigned a0 = f2tf32(odd ? t1 : t0);
            unsigned a1 = f2tf32(odd ? t3 : t2);
            unsigned a2 = f2tf32(odd ? u1 : u0);
            unsigned a3 = f2tf32(odd ? u3 : u2);
            #pragma unroll
            for (int nt = 0; nt < 8; nt++) {
                unsigned b0 = __float_as_uint(Vs[(kc * 8 + q)     * VS_STRIDE + nt * 8 + g]);
                unsigned b1 = __float_as_uint(Vs[(kc * 8 + q + 4) * VS_STRIDE + nt * 8 + g]);
                asm volatile(
                    "mma.sync.aligned.m16n8k8.row.col.f32.tf32.tf32.f32 "
                    "{%0,%1,%2,%3}, {%4,%5,%6,%7}, {%8,%9}, {%0,%1,%2,%3};"
                    : "+f"(o[nt][0]), "+f"(o[nt][1]), "+f"(o[nt][2]), "+f"(o[nt][3])
                    : "r"(a0), "r"(a1), "r"(a2), "r"(a3), "r"(b0), "r"(b1));
            }
        }
    }

    float inv0 = 1.0f / l0, inv1 = 1.0f / l1;
    int srow0 = q0 + row_a;
    int srow1 = srow0 + 8;
    #pragma unroll
    for (int nt = 0; nt < 8; nt++) {
        int c = h * 64 + nt * 8 + 2 * q;
        *(float2*)(O + ((size_t)srow0 * BATCH + b) * DMODEL + c) =
            make_float2(tf32r(o[nt][0] * inv0), tf32r(o[nt][1] * inv0));
        *(float2*)(O + ((size_t)srow1 * BATCH + b) * DMODEL + c) =
            make_float2(tf32r(o[nt][2] * inv1), tf32r(o[nt][3] * inv1));
    }
}

// ---------------- host orchestration ----------------
extern "C" void kernel_launch(void* const* d_in, const int* in_sizes, int n_in,
                              void* d_out, int out_size)
{
    const float* x   = (const float*)d_in[0];
    const float* n1w = (const float*)d_in[1];
    const float* wq  = (const float*)d_in[2];
    const float* bq  = (const float*)d_in[3];
    const float* wk  = (const float*)d_in[4];
    const float* bk  = (const float*)d_in[5];
    const float* wv  = (const float*)d_in[6];
    const float* bv  = (const float*)d_in[7];
    const float* qnw = (const float*)d_in[8];
    const float* knw = (const float*)d_in[9];
    const float* wo  = (const float*)d_in[10];
    const float* bo  = (const float*)d_in[11];
    const float* n2w = (const float*)d_in[12];
    const float* w1  = (const float*)d_in[13];
    const float* b1  = (const float*)d_in[14];
    const float* w2  = (const float*)d_in[15];
    const float* b2  = (const float*)d_in[16];

    float *ph, *pwqkv, *pbqkv, *pqkv, *pq, *pk, *pv, *pattn, *px1, *ph2, *pmid;
    float *pwor, *pw1r, *pw2r;
    cudaGetSymbolAddress((void**)&ph,    g_h);
    cudaGetSymbolAddress((void**)&pwqkv, g_wqkv);
    cudaGetSymbolAddress((void**)&pbqkv, g_bqkv);
    cudaGetSymbolAddress((void**)&pqkv,  g_qkv);
    cudaGetSymbolAddress((void**)&pq,    g_q);
    cudaGetSymbolAddress((void**)&pk,    g_k);
    cudaGetSymbolAddress((void**)&pv,    g_v);
    cudaGetSymbolAddress((void**)&pattn, g_attn);
    cudaGetSymbolAddress((void**)&px1,   g_x1);
    cudaGetSymbolAddress((void**)&ph2,   g_h2);
    cudaGetSymbolAddress((void**)&pmid,  g_mid);
    cudaGetSymbolAddress((void**)&pwor,  g_wor);
    cudaGetSymbolAddress((void**)&pw1r,  g_w1r);
    cudaGetSymbolAddress((void**)&pw2r,  g_w2r);

    cudaFuncSetAttribute(attn_tc_kernel,
                         cudaFuncAttributeMaxDynamicSharedMemorySize, ATTN_SMEM_BYTES);
    cudaFuncSetAttribute(gemm_tf32_kernel<0>,
                         cudaFuncAttributeMaxDynamicSharedMemorySize, GEMM_SMEM_BYTES);
    cudaFuncSetAttribute(gemm_tf32_kernel<1>,
                         cudaFuncAttributeMaxDynamicSharedMemorySize, GEMM_SMEM_BYTES);
    cudaFuncSetAttribute(gemm_tf32_kernel<2>,
                         cudaFuncAttributeMaxDynamicSharedMemorySize, GEMM_SMEM_BYTES);

    pack_wqkv_kernel<<<(DMODEL * QKVN + 255) / 256, 256>>>(wq, wk, wv, bq, bk, bv, pwqkv, pbqkv);
    roundcopy_kernel<<<(DMODEL * DMODEL / 4 + 255) / 256, 256>>>(wo, pwor, DMODEL * DMODEL / 4);
    roundcopy_kernel<<<(DMODEL * DFF / 4 + 255) / 256, 256>>>(w1, pw1r, DMODEL * DFF / 4);
    roundcopy_kernel<<<(DFF * DMODEL / 4 + 255) / 256, 256>>>(w2, pw2r, DFF * DMODEL / 4);
    rmsnorm_kernel<<<NTOK, 256>>>(x, n1w, ph);
    gemm_tf32_kernel<0><<<dim3(QKVN / 128, NTOK / 128), 128, GEMM_SMEM_BYTES>>>(
        ph, pwqkv, pbqkv, nullptr, pqkv, NTOK, QKVN, DMODEL);
    qkrope_kernel<<<dim3(NTOK, 6), dim3(64, 4)>>>(pqkv, qnw, knw, pq, pk, pv);
    attn_tc_kernel<<<dim3(S_LEN / 64, BATCH * NHEAD), 128, ATTN_SMEM_BYTES>>>(pq, pk, pv, pattn);
    gemm_tf32_kernel<2><<<dim3(DMODEL / 128, NTOK / 128), 128, GEMM_SMEM_BYTES>>>(
        pattn, pwor, bo, x, px1, NTOK, DMODEL, DMODEL);
    rmsnorm_kernel<<<NTOK, 256>>>(px1, n2w, ph2);
    gemm_tf32_kernel<1><<<dim3(DFF / 128, NTOK / 128), 128, GEMM_SMEM_BYTES>>>(
        ph2, pw1r, b1, nullptr, pmid, NTOK, DFF, DMODEL);
    gemm_tf32_kernel<2><<<dim3(DMODEL / 128, NTOK / 128), 128, GEMM_SMEM_BYTES>>>(
        pmid, pw2r, b2, px1, (float*)d_out, NTOK, DMODEL, DFF);
}

// round 10
// speedup vs baseline: 4.8547x; 1.4860x over previous
#include <cuda_runtime.h>
#include <cuda_fp16.h>
#include <math.h>
#include <stdint.h>

#define S_LEN   2048
#define BATCH   2
#define DMODEL  1024
#define NHEAD   16
#define NKV     4
#define HEADDIM 64
#define NTOK    4096            // S_LEN * BATCH
#define DFF     4096            // 4 * DMODEL
#define QKVN    1536            // 1024 + 256 + 256
#define EPS_F   1e-5f
#define QK_SCALE 0.03125f       // D^-0.5 = 1/32

// attention smem layout (floats)
#define QS_STRIDE 68
#define KS_STRIDE 68
#define VS_STRIDE 72
#define ATTN_SMEM_FLOATS (64*QS_STRIDE + 64*KS_STRIDE + 64*VS_STRIDE)
#define ATTN_SMEM_BYTES  (ATTN_SMEM_FLOATS * 4)

// fp16 GEMM smem: 4 stages, tiles [128 rows][40 halfs] (stride 80B, 64B data + 16B pad)
#define GF_TILE_BYTES 10240     // 128*80
#define GF_STAGES 4
#define GF_SMEM_BYTES (2 * GF_STAGES * GF_TILE_BYTES)   // 81920

// ---------------- scratch (__device__ globals; no allocation allowed) ----------------
__device__ __half g_h   [NTOK * DMODEL];
__device__ __half g_wqkv[QKVN * DMODEL];      // transposed [N,K]
__device__ float  g_bqkv[QKVN];
__device__ float  g_qkv [NTOK * QKVN];
__device__ float  g_q   [BATCH * NHEAD * S_LEN * HEADDIM];
__device__ float  g_k   [BATCH * NKV   * S_LEN * HEADDIM];
__device__ float  g_v   [BATCH * NKV   * S_LEN * HEADDIM];
__device__ __half g_attn[NTOK * DMODEL];
__device__ float  g_x1  [NTOK * DMODEL];
__device__ __half g_h2  [NTOK * DMODEL];
__device__ __half g_mid [NTOK * DFF];
__device__ __half g_wor [DMODEL * DMODEL];    // transposed
__device__ __half g_w1r [DFF * DMODEL];       // transposed [4096][1024]
__device__ __half g_w2r [DMODEL * DFF];       // transposed [1024][4096]

__device__ __forceinline__ unsigned f2tf32(float x) {
    unsigned u;
    asm("cvt.rna.tf32.f32 %0, %1;" : "=r"(u) : "f"(x));
    return u;
}
__device__ __forceinline__ float tf32r(float x) { return __uint_as_float(f2tf32(x)); }

__device__ __forceinline__ void cp16s(uint32_t daddr, const void* src) {
    asm volatile("cp.async.ca.shared.global [%0], [%1], 16;" :: "r"(daddr), "l"(src));
}

// ---------------- pack wq|wk|wv transposed: Wt[c][k] fp16 ----------------
__global__ __launch_bounds__(256)
void pack_wqkv_t_kernel(const float* __restrict__ wq, const float* __restrict__ wk,
                        const float* __restrict__ wv, __half* __restrict__ Wt)
{
    __shared__ float t[32][33];
    int bx = blockIdx.x * 32;   // c base
    int by = blockIdx.y * 32;   // k base
    int tx = threadIdx.x & 31;
    int ty = threadIdx.x >> 5;
    #pragma unroll
    for (int j = 0; j < 4; j++) {
        int k = by + ty + 8 * j;
        int c = bx + tx;
        float v;
        if (c < 1024)       v = wq[(size_t)k * 1024 + c];
        else if (c < 1280)  v = wk[(size_t)k * 256 + (c - 1024)];
        else                v = wv[(size_t)k * 256 + (c - 1280)];
        t[ty + 8 * j][tx] = v;
    }
    __syncthreads();
    #pragma unroll
    for (int j = 0; j < 4; j++) {
        int c = bx + ty + 8 * j;
        Wt[(size_t)c * DMODEL + by + tx] = __float2half_rn(t[tx][ty + 8 * j]);
    }
}

// ---------------- fp16 transpose: dst[C][R] = half(src[R][C]) ----------------
__global__ __launch_bounds__(256)
void transpose_h_kernel(const float* __restrict__ src, __half* __restrict__ dst,
                        int R, int C)
{
    __shared__ float t[32][33];
    int bx = blockIdx.x * 32;   // C base
    int by = blockIdx.y * 32;   // R base
    int tx = threadIdx.x & 31;
    int ty = threadIdx.x >> 5;
    #pragma unroll
    for (int j = 0; j < 4; j++)
        t[ty + 8 * j][tx] = src[(size_t)(by + ty + 8 * j) * C + bx + tx];
    __syncthreads();
    #pragma unroll
    for (int j = 0; j < 4; j++)
        dst[(size_t)(bx + ty + 8 * j) * R + by + tx] = __float2half_rn(t[tx][ty + 8 * j]);
}

__global__ void packbias_kernel(const float* __restrict__ bq, const float* __restrict__ bk,
                                const float* __restrict__ bv, float* __restrict__ bias)
{
    int i = blockIdx.x * 256 + threadIdx.x;
    if (i < QKVN)
        bias[i] = (i < 1024) ? bq[i] : (i < 1280 ? bk[i - 1024] : bv[i - 1280]);
}

// ---------------- RMSNorm over D=1024, fp16 output ----------------
__global__ __launch_bounds__(256)
void rmsnorm_kernel(const float* __restrict__ x, const float* __restrict__ w,
                    __half* __restrict__ y)
{
    int row = blockIdx.x;
    int i = threadIdx.x;
    const float* xr = x + (size_t)row * DMODEL;
    float4 xv = *(const float4*)(xr + i * 4);
    float ss = xv.x * xv.x + xv.y * xv.y + xv.z * xv.z + xv.w * xv.w;
    #pragma unroll
    for (int off = 16; off; off >>= 1) ss += __shfl_xor_sync(0xffffffffu, ss, off);
    __shared__ float red[8];
    __shared__ float s_sc;
    if ((i & 31) == 0) red[i >> 5] = ss;
    __syncthreads();
    if (i == 0) {
        float tot = 0.f;
        #pragma unroll
        for (int kk = 0; kk < 8; kk++) tot += red[kk];
        s_sc = rsqrtf(tot * (1.0f / DMODEL) + EPS_F);
    }
    __syncthreads();
    float sc = s_sc;
    float4 wv = *(const float4*)(w + i * 4);
    __half2 h0 = __floats2half2_rn(xv.x * sc * wv.x, xv.y * sc * wv.y);
    __half2 h1 = __floats2half2_rn(xv.z * sc * wv.z, xv.w * sc * wv.w);
    uint2 u;
    u.x = *(unsigned*)&h0;
    u.y = *(unsigned*)&h1;
    *(uint2*)(y + (size_t)row * DMODEL + i * 4) = u;
}

// ---------------- per-head QK RMSNorm + RoPE + relayout; V relayout ----------------
__global__ __launch_bounds__(256)
void qkrope_kernel(const float* __restrict__ qkv, const float* __restrict__ qn_w,
                   const float* __restrict__ kn_w, float* __restrict__ Qo,
                   float* __restrict__ Ko, float* __restrict__ Vo)
{
    int t = blockIdx.x;            // token = s*BATCH + b
    int ty = threadIdx.y;          // 0..3
    int slot = blockIdx.y * 4 + ty;
    int i = threadIdx.x;           // 0..63
    int s = t / BATCH, b = t % BATCH;
    __shared__ float buf[4][64];
    __shared__ float red[4][2];

    if (slot >= 20) {   // V: pure relayout (whole block is V)
        int vh = slot - 20;
        float v = qkv[(size_t)t * QKVN + 1280 + vh * 64 + i];
        Vo[((size_t)(b * NKV + vh) * S_LEN + s) * 64 + i] = v;
        return;
    }

    bool is_q = (slot < 16);
    int col = is_q ? (slot * 64 + i) : (1024 + (slot - 16) * 64 + i);
    float v = qkv[(size_t)t * QKVN + col];
    float ss = v * v;
    #pragma unroll
    for (int off = 16; off; off >>= 1) ss += __shfl_xor_sync(0xffffffffu, ss, off);
    if ((i & 31) == 0) red[ty][i >> 5] = ss;
    __syncthreads();
    float tot = red[ty][0] + red[ty][1];
    float sc = rsqrtf(tot * (1.0f / 64.0f) + EPS_F);
    const float* w = is_q ? qn_w : kn_w;
    float nv = v * sc * w[i];
    buf[ty][i] = nv;
    __syncthreads();
    float rot = (i < 32) ? -buf[ty][i + 32] : buf[ty][i - 32];
    int j = i & 31;
    float invf = exp2f(-(float)j * (13.287712379549449f / 32.0f));
    float ang = (float)s * invf;
    float sn, cs;
    sincosf(ang, &sn, &cs);
    float outv = nv * cs + rot * sn;
    if (is_q) {
        outv *= QK_SCALE;
        Qo[((size_t)(b * NHEAD + slot) * S_LEN + s) * 64 + i] = outv;
    } else {
        Ko[((size_t)(b * NKV + (slot - 16)) * S_LEN + s) * 64 + i] = outv;
    }
}

// ---------------- fp16 GEMM stage loader: 8 cp.async per thread ----------------
__device__ __forceinline__ void gf_load(uint32_t sA, uint32_t sB,
                                        const __half* Ag, const __half* Bg,
                                        int K, int k0, int tid)
{
    int r0 = tid >> 2;             // 0..31
    int ch = (tid & 3) << 3;       // half offset in row: 0,8,16,24
    #pragma unroll
    for (int j = 0; j < 4; j++) {
        int r = r0 + 32 * j;
        uint32_t so = (uint32_t)(r * 80 + ch * 2);
        cp16s(sA + so, Ag + (size_t)r * K + k0 + ch);
        cp16s(sB + so, Bg + (size_t)r * K + k0 + ch);
    }
    asm volatile("cp.async.commit_group;" ::: "memory");
}

// ---------------- fp16 GEMM: C[M,N] = A[M,K] @ Bt[N,K]^T + bias (+epilogue) ----------
// EPI: 0 = +bias (fp32 out), 1 = gelu(+bias) (fp16 out), 2 = +bias+residual (fp32 out)
// block 128x128, BK=32, 4 warps of 64x64, mma.sync.m16n8k16.f16, fp32 accum.
template<int EPI>
__global__ __launch_bounds__(128)
void gemm_f16_kernel(const __half* __restrict__ A, const __half* __restrict__ Bt,
                     const float* __restrict__ bias, const float* __restrict__ res,
                     void* __restrict__ Cout, int M, int N, int K)
{
    extern __shared__ char smc[];
    uint32_t smem_base;
    asm("{ .reg .u64 t; cvta.to.shared.u64 t, %1; cvt.u32.u64 %0, t; }"
        : "=r"(smem_base) : "l"(smc));

    int tid  = threadIdx.x;
    int wid  = tid >> 5, lane = tid & 31;
    int g    = lane >> 2;
    int q    = lane & 3;
    int wm   = (wid >> 1) * 64;
    int wn   = (wid & 1) * 64;

    int row0 = blockIdx.y * 128;
    int col0 = blockIdx.x * 128;
    const __half* Ag = A  + (size_t)row0 * K;
    const __half* Bg = Bt + (size_t)col0 * K;

    float acc[4][8][4];
    #pragma unroll
    for (int mt = 0; mt < 4; mt++)
        #pragma unroll
        for (int nt = 0; nt < 8; nt++)
            #pragma unroll
            for (int r = 0; r < 4; r++) acc[mt][nt][r] = 0.f;

    const int KT = K >> 5;

    #pragma unroll
    for (int st = 0; st < 3; st++)
        gf_load(smem_base + st * GF_TILE_BYTES,
                smem_base + (GF_STAGES + st) * GF_TILE_BYTES,
                Ag, Bg, K, st * 32, tid);

    for (int kt = 0; kt < KT; kt++) {
        asm volatile("cp.async.wait_group 2;" ::: "memory");
        __syncthreads();

        if (kt + 3 < KT) {
            int st = (kt + 3) & 3;
            gf_load(smem_base + st * GF_TILE_BYTES,
                    smem_base + (GF_STAGES + st) * GF_TILE_BYTES,
                    Ag, Bg, K, (kt + 3) * 32, tid);
        }

        int st = kt & 3;
        const __half* As = (const __half*)(smc + st * GF_TILE_BYTES);
        const __half* Bs = (const __half*)(smc + (GF_STAGES + st) * GF_TILE_BYTES);

        #pragma unroll
        for (int kk = 0; kk < 32; kk += 16) {
            unsigned af[4][4];
            #pragma unroll
            for (int mt = 0; mt < 4; mt++) {
                int r = wm + mt * 16 + g;
                af[mt][0] = *(const unsigned*)(As + r * 40 + kk + 2 * q);
                af[mt][1] = *(const unsigned*)(As + (r + 8) * 40 + kk + 2 * q);
                af[mt][2] = *(const unsigned*)(As + r * 40 + kk + 2 * q + 8);
                af[mt][3] = *(const unsigned*)(As + (r + 8) * 40 + kk + 2 * q + 8);
            }
            unsigned bf[8][2];
            #pragma unroll
            for (int nt = 0; nt < 8; nt++) {
                int c = wn + nt * 8 + g;
                bf[nt][0] = *(const unsigned*)(Bs + c * 40 + kk + 2 * q);
                bf[nt][1] = *(const unsigned*)(Bs + c * 40 + kk + 2 * q + 8);
            }
            #pragma unroll
            for (int mt = 0; mt < 4; mt++)
                #pragma unroll
                for (int nt = 0; nt < 8; nt++) {
                    asm volatile(
                        "mma.sync.aligned.m16n8k16.row.col.f32.f16.f16.f32 "
                        "{%0,%1,%2,%3}, {%4,%5,%6,%7}, {%8,%9}, {%0,%1,%2,%3};"
                        : "+f"(acc[mt][nt][0]), "+f"(acc[mt][nt][1]),
                          "+f"(acc[mt][nt][2]), "+f"(acc[mt][nt][3])
                        : "r"(af[mt][0]), "r"(af[mt][1]), "r"(af[mt][2]), "r"(af[mt][3]),
                          "r"(bf[nt][0]), "r"(bf[nt][1]));
                }
        }
    }

    #pragma unroll
    for (int mt = 0; mt < 4; mt++) {
        int r = row0 + wm + mt * 16 + g;
        #pragma unroll
        for (int nt = 0; nt < 8; nt++) {
            int c = col0 + wn + nt * 8 + 2 * q;
            float bv0 = bias[c], bv1 = bias[c + 1];
            float v00 = acc[mt][nt][0] + bv0;
            float v01 = acc[mt][nt][1] + bv1;
            float v10 = acc[mt][nt][2] + bv0;
            float v11 = acc[mt][nt][3] + bv1;
            if (EPI == 1) {
                v00 = 0.5f * v00 * (1.0f + erff(v00 * 0.70710678118654752f));
                v01 = 0.5f * v01 * (1.0f + erff(v01 * 0.70710678118654752f));
                v10 = 0.5f * v10 * (1.0f + erff(v10 * 0.70710678118654752f));
                v11 = 0.5f * v11 * (1.0f + erff(v11 * 0.70710678118654752f));
                __half* C = (__half*)Cout;
                __half2 h0 = __floats2half2_rn(v00, v01);
                __half2 h1 = __floats2half2_rn(v10, v11);
                *(__half2*)(C + (size_t)r * N + c)       = h0;
                *(__half2*)(C + (size_t)(r + 8) * N + c) = h1;
            } else {
                float* C = (float*)Cout;
                if (EPI == 2) {
                    float2 r0 = *(const float2*)(res + (size_t)r * N + c);
                    float2 r1 = *(const float2*)(res + (size_t)(r + 8) * N + c);
                    v00 += r0.x; v01 += r0.y;
                    v10 += r1.x; v11 += r1.y;
                }
                *(float2*)(C + (size_t)r * N + c)       = make_float2(v00, v01);
                *(float2*)(C + (size_t)(r + 8) * N + c) = make_float2(v10, v11);
            }
        }
    }
}

// ---------------- TF32 tensor-core flash attention (fp16 output) ----------------
__global__ __launch_bounds__(128)
void attn_tc_kernel(const float* __restrict__ Q, const float* __restrict__ K,
                    const float* __restrict__ V, __half* __restrict__ O)
{
    extern __shared__ float sm[];
    float* Qs = sm;
    float* Ks = sm + 64 * QS_STRIDE;
    float* Vs = sm + 64 * (QS_STRIDE + KS_STRIDE);

    int tid  = threadIdx.x;
    int wid  = tid >> 5, lane = tid & 31;
    int g    = lane >> 2;
    int q    = lane & 3;
    int qt   = blockIdx.x;
    int bh   = blockIdx.y;
    int b    = bh >> 4;
    int h    = bh & 15;
    int kvh  = h >> 2;
    int q0   = qt * 64;

    const float* Qb = Q + (size_t)(b * NHEAD + h)  * S_LEN * 64 + (size_t)q0 * 64;
    const float* Kb = K + (size_t)(b * NKV  + kvh) * S_LEN * 64;
    const float* Vb = V + (size_t)(b * NKV  + kvh) * S_LEN * 64;

    for (int i = tid; i < 64 * 16; i += 128) {
        int r = i >> 4, c = (i & 15) << 2;
        float4 v = *(const float4*)(Qb + (size_t)r * 64 + c);
        *(float4*)&Qs[r * QS_STRIDE + c] = make_float4(tf32r(v.x), tf32r(v.y),
                                                       tf32r(v.z), tf32r(v.w));
    }

    float m0 = -INFINITY, m1 = -INFINITY, l0 = 0.f, l1 = 0.f;
    float o[8][4];
    #pragma unroll
    for (int nt = 0; nt < 8; nt++)
        #pragma unroll
        for (int r = 0; r < 4; r++) o[nt][r] = 0.f;

    int row_a = 16 * wid + g;
    int nkt = qt + 1;

    for (int jt = 0; jt < nkt; ++jt) {
        int j0 = jt * 64;
        __syncthreads();
        for (int i = tid; i < 64 * 16; i += 128) {
            int r = i >> 4, c = (i & 15) << 2;
            float4 kv = *(const float4*)(Kb + (size_t)(j0 + r) * 64 + c);
            *(float4*)&Ks[r * KS_STRIDE + c] = make_float4(tf32r(kv.x), tf32r(kv.y),
                                                           tf32r(kv.z), tf32r(kv.w));
            float4 vv = *(const float4*)(Vb + (size_t)(j0 + r) * 64 + c);
            *(float4*)&Vs[r * VS_STRIDE + c] = make_float4(tf32r(vv.x), tf32r(vv.y),
                                                           tf32r(vv.z), tf32r(vv.w));
        }
        __syncthreads();

        float s[8][4];
        #pragma unroll
        for (int nt = 0; nt < 8; nt++)
            #pragma unroll
            for (int r = 0; r < 4; r++) s[nt][r] = 0.f;

        #pragma unroll
        for (int k0 = 0; k0 < 64; k0 += 8) {
            unsigned a0 = __float_as_uint(Qs[(row_a)     * QS_STRIDE + k0 + q]);
            unsigned a1 = __float_as_uint(Qs[(row_a + 8) * QS_STRIDE + k0 + q]);
            unsigned a2 = __float_as_uint(Qs[(row_a)     * QS_STRIDE + k0 + q + 4]);
            unsigned a3 = __float_as_uint(Qs[(row_a + 8) * QS_STRIDE + k0 + q + 4]);
            #pragma unroll
            for (int nt = 0; nt < 8; nt++) {
                unsigned b0 = __float_as_uint(Ks[(nt * 8 + g) * KS_STRIDE + k0 + q]);
                unsigned b1 = __float_as_uint(Ks[(nt * 8 + g) * KS_STRIDE + k0 + q + 4]);
                asm volatile(
                    "mma.sync.aligned.m16n8k8.row.col.f32.tf32.tf32.f32 "
                    "{%0,%1,%2,%3}, {%4,%5,%6,%7}, {%8,%9}, {%0,%1,%2,%3};"
                    : "+f"(s[nt][0]), "+f"(s[nt][1]), "+f"(s[nt][2]), "+f"(s[nt][3])
                    : "r"(a0), "r"(a1), "r"(a2), "r"(a3), "r"(b0), "r"(b1));
            }
        }

        if (jt == qt) {
            #pragma unroll
            for (int nt = 0; nt < 8; nt++) {
                int col = nt * 8 + 2 * q;
                if (col     > row_a)     s[nt][0] = -INFINITY;
                if (col + 1 > row_a)     s[nt][1] = -INFINITY;
                if (col     > row_a + 8) s[nt][2] = -INFINITY;
                if (col + 1 > row_a + 8) s[nt][3] = -INFINITY;
            }
        }

        float mt0 = -INFINITY, mt1 = -INFINITY;
        #pragma unroll
        for (int nt = 0; nt < 8; nt++) {
            mt0 = fmaxf(mt0, fmaxf(s[nt][0], s[nt][1]));
            mt1 = fmaxf(mt1, fmaxf(s[nt][2], s[nt][3]));
        }
        #pragma unroll
        for (int off = 1; off < 4; off <<= 1) {
            mt0 = fmaxf(mt0, __shfl_xor_sync(0xffffffffu, mt0, off));
            mt1 = fmaxf(mt1, __shfl_xor_sync(0xffffffffu, mt1, off));
        }
        float mn0 = fmaxf(m0, mt0), mn1 = fmaxf(m1, mt1);
        float al0 = __expf(m0 - mn0), al1 = __expf(m1 - mn1);
        m0 = mn0; m1 = mn1;
        float ps0 = 0.f, ps1 = 0.f;
        #pragma unroll
        for (int nt = 0; nt < 8; nt++) {
            s[nt][0] = __expf(s[nt][0] - mn0);
            s[nt][1] = __expf(s[nt][1] - mn0);
            s[nt][2] = __expf(s[nt][2] - mn1);
            s[nt][3] = __expf(s[nt][3] - mn1);
            ps0 += s[nt][0] + s[nt][1];
            ps1 += s[nt][2] + s[nt][3];
            o[nt][0] *= al0; o[nt][1] *= al0;
            o[nt][2] *= al1; o[nt][3] *= al1;
        }
        #pragma unroll
        for (int off = 1; off < 4; off <<= 1) {
            ps0 += __shfl_xor_sync(0xffffffffu, ps0, off);
            ps1 += __shfl_xor_sync(0xffffffffu, ps1, off);
        }
        l0 = l0 * al0 + ps0;
        l1 = l1 * al1 + ps1;

        int base  = lane & ~3;
        int srcLo = base + (q >> 1);
        int srcHi = base + 2 + (q >> 1);
        bool odd  = q & 1;
        #pragma unroll
        for (int kc = 0; kc < 8; kc++) {
            float p0 = s[kc][0], p1 = s[kc][1], p2 = s[kc][2], p3 = s[kc][3];
            float t0 = __shfl_sync(0xffffffffu, p0, srcLo);
            float t1 = __shfl_sync(0xffffffffu, p1, srcLo);
            float t2 = __shfl_sync(0xffffffffu, p2, srcLo);
            float t3 = __shfl_sync(0xffffffffu, p3, srcLo);
            float u0 = __shfl_sync(0xffffffffu, p0, srcHi);
            float u1 = __shfl_sync(0xffffffffu, p1, srcHi);
            float u2 = __shfl_sync(0xffffffffu, p2, srcHi);
            float u3 = __shfl_sync(0xffffffffu, p3, srcHi);
            unsigned a0 = f2tf32(odd ? t1 : t0);
            unsigned a1 = f2tf32(odd ? t3 : t2);
            unsigned a2 = f2tf32(odd ? u1 : u0);
            unsigned a3 = f2tf32(odd ? u3 : u2);
            #pragma unroll
            for (int nt = 0; nt < 8; nt++) {
                unsigned b0 = __float_as_uint(Vs[(kc * 8 + q)     * VS_STRIDE + nt * 8 + g]);
                unsigned b1 = __float_as_uint(Vs[(kc * 8 + q + 4) * VS_STRIDE + nt * 8 + g]);
                asm volatile(
                    "mma.sync.aligned.m16n8k8.row.col.f32.tf32.tf32.f32 "
                    "{%0,%1,%2,%3}, {%4,%5,%6,%7}, {%8,%9}, {%0,%1,%2,%3};"
                    : "+f"(o[nt][0]), "+f"(o[nt][1]), "+f"(o[nt][2]), "+f"(o[nt][3])
                    : "r"(a0), "r"(a1), "r"(a2), "r"(a3), "r"(b0), "r"(b1));
            }
        }
    }

    float inv0 = 1.0f / l0, inv1 = 1.0f / l1;
    int srow0 = q0 + row_a;
    int srow1 = srow0 + 8;
    #pragma unroll
    for (int nt = 0; nt < 8; nt++) {
        int c = h * 64 + nt * 8 + 2 * q;
        *(__half2*)(O + ((size_t)srow0 * BATCH + b) * DMODEL + c) =
            __floats2half2_rn(o[nt][0] * inv0, o[nt][1] * inv0);
        *(__half2*)(O + ((size_t)srow1 * BATCH + b) * DMODEL + c) =
            __floats2half2_rn(o[nt][2] * inv1, o[nt][3] * inv1);
    }
}

// ---------------- host orchestration ----------------
extern "C" void kernel_launch(void* const* d_in, const int* in_sizes, int n_in,
                              void* d_out, int out_size)
{
    const float* x   = (const float*)d_in[0];
    const float* n1w = (const float*)d_in[1];
    const float* wq  = (const float*)d_in[2];
    const float* bq  = (const float*)d_in[3];
    const float* wk  = (const float*)d_in[4];
    const float* bk  = (const float*)d_in[5];
    const float* wv  = (const float*)d_in[6];
    const float* bv  = (const float*)d_in[7];
    const float* qnw = (const float*)d_in[8];
    const float* knw = (const float*)d_in[9];
    const float* wo  = (const float*)d_in[10];
    const float* bo  = (const float*)d_in[11];
    const float* n2w = (const float*)d_in[12];
    const float* w1  = (const float*)d_in[13];
    const float* b1  = (const float*)d_in[14];
    const float* w2  = (const float*)d_in[15];
    const float* b2  = (const float*)d_in[16];

    __half *ph, *pwqkv, *pattn, *ph2, *pmid, *pwor, *pw1r, *pw2r;
    float *pbqkv, *pqkv, *pq, *pk, *pv, *px1;
    cudaGetSymbolAddress((void**)&ph,    g_h);
    cudaGetSymbolAddress((void**)&pwqkv, g_wqkv);
    cudaGetSymbolAddress((void**)&pbqkv, g_bqkv);
    cudaGetSymbolAddress((void**)&pqkv,  g_qkv);
    cudaGetSymbolAddress((void**)&pq,    g_q);
    cudaGetSymbolAddress((void**)&pk,    g_k);
    cudaGetSymbolAddress((void**)&pv,    g_v);
    cudaGetSymbolAddress((void**)&pattn, g_attn);
    cudaGetSymbolAddress((void**)&px1,   g_x1);
    cudaGetSymbolAddress((void**)&ph2,   g_h2);
    cudaGetSymbolAddress((void**)&pmid,  g_mid);
    cudaGetSymbolAddress((void**)&pwor,  g_wor);
    cudaGetSymbolAddress((void**)&pw1r,  g_w1r);
    cudaGetSymbolAddress((void**)&pw2r,  g_w2r);

    cudaFuncSetAttribute(attn_tc_kernel,
                         cudaFuncAttributeMaxDynamicSharedMemorySize, ATTN_SMEM_BYTES);
    cudaFuncSetAttribute(gemm_f16_kernel<0>,
                         cudaFuncAttributeMaxDynamicSharedMemorySize, GF_SMEM_BYTES);
    cudaFuncSetAttribute(gemm_f16_kernel<1>,
                         cudaFuncAttributeMaxDynamicSharedMemorySize, GF_SMEM_BYTES);
    cudaFuncSetAttribute(gemm_f16_kernel<2>,
                         cudaFuncAttributeMaxDynamicSharedMemorySize, GF_SMEM_BYTES);

    // weight prep (fp16 transposes to [N,K])
    pack_wqkv_t_kernel<<<dim3(QKVN / 32, DMODEL / 32), 256>>>(wq, wk, wv, pwqkv);
    packbias_kernel<<<6, 256>>>(bq, bk, bv, pbqkv);
    transpose_h_kernel<<<dim3(DMODEL / 32, DMODEL / 32), 256>>>(wo, pwor, DMODEL, DMODEL);
    transpose_h_kernel<<<dim3(DFF / 32, DMODEL / 32), 256>>>(w1, pw1r, DMODEL, DFF);
    transpose_h_kernel<<<dim3(DMODEL / 32, DFF / 32), 256>>>(w2, pw2r, DFF, DMODEL);

    rmsnorm_kernel<<<NTOK, 256>>>(x, n1w, ph);
    gemm_f16_kernel<0><<<dim3(QKVN / 128, NTOK / 128), 128, GF_SMEM_BYTES>>>(
        ph, pwqkv, pbqkv, nullptr, pqkv, NTOK, QKVN, DMODEL);
    qkrope_kernel<<<dim3(NTOK, 6), dim3(64, 4)>>>(pqkv, qnw, knw, pq, pk, pv);
    attn_tc_kernel<<<dim3(S_LEN / 64, BATCH * NHEAD), 128, ATTN_SMEM_BYTES>>>(pq, pk, pv, pattn);
    gemm_f16_kernel<2><<<dim3(DMODEL / 128, NTOK / 128), 128, GF_SMEM_BYTES>>>(
        pattn, pwor, bo, x, px1, NTOK, DMODEL, DMODEL);
    rmsnorm_kernel<<<NTOK, 256>>>(px1, n2w, ph2);
    gemm_f16_kernel<1><<<dim3(DFF / 128, NTOK / 128), 128, GF_SMEM_BYTES>>>(
        ph2, pw1r, b1, nullptr, pmid, NTOK, DFF, DMODEL);
    gemm_f16_kernel<2><<<dim3(DMODEL / 128, NTOK / 128), 128, GF_SMEM_BYTES>>>(
        pmid, pw2r, b2, px1, d_out, NTOK, DMODEL, DFF);
}

// round 11
// speedup vs baseline: 5.6461x; 1.1630x over previous
#include <cuda_runtime.h>
#include <cuda_fp16.h>
#include <math.h>
#include <stdint.h>

#define S_LEN   2048
#define BATCH   2
#define DMODEL  1024
#define NHEAD   16
#define NKV     4
#define HEADDIM 64
#define NTOK    4096            // S_LEN * BATCH
#define DFF     4096            // 4 * DMODEL
#define QKVN    1536            // 1024 + 256 + 256
#define EPS_F   1e-5f
#define QK_SCALE 0.03125f       // D^-0.5 = 1/32

// fp16 GEMM smem: 4 stages, tiles [128 rows][40 halfs] (stride 80B)
#define GF_TILE_BYTES 10240     // 128*80
#define GF_STAGES 4
#define GF_SMEM_BYTES (2 * GF_STAGES * GF_TILE_BYTES)   // 81920

// ---------------- scratch (__device__ globals; no allocation allowed) ----------------
__device__ __half g_h   [NTOK * DMODEL];
__device__ __half g_wqkv[QKVN * DMODEL];      // transposed [N,K]
__device__ float  g_bqkv[QKVN];
__device__ float  g_qkv [NTOK * QKVN];
__device__ __half g_q   [BATCH * NHEAD * S_LEN * HEADDIM];
__device__ __half g_k   [BATCH * NKV   * S_LEN * HEADDIM];
__device__ __half g_v   [BATCH * NKV   * S_LEN * HEADDIM];
__device__ __half g_attn[NTOK * DMODEL];
__device__ float  g_x1  [NTOK * DMODEL];
__device__ __half g_h2  [NTOK * DMODEL];
__device__ __half g_mid [NTOK * DFF];
__device__ __half g_wor [DMODEL * DMODEL];    // transposed
__device__ __half g_w1r [DFF * DMODEL];       // transposed
__device__ __half g_w2r [DMODEL * DFF];       // transposed

__device__ __forceinline__ void cp16s(uint32_t daddr, const void* src) {
    asm volatile("cp.async.ca.shared.global [%0], [%1], 16;" :: "r"(daddr), "l"(src));
}
__device__ __forceinline__ unsigned packh2(float a, float b) {
    __half2 h = __floats2half2_rn(a, b);
    return *(unsigned*)&h;
}

// ---------------- pack wq|wk|wv transposed: Wt[c][k] fp16 ----------------
__global__ __launch_bounds__(256)
void pack_wqkv_t_kernel(const float* __restrict__ wq, const float* __restrict__ wk,
                        const float* __restrict__ wv, __half* __restrict__ Wt)
{
    __shared__ float t[32][33];
    int bx = blockIdx.x * 32;   // c base
    int by = blockIdx.y * 32;   // k base
    int tx = threadIdx.x & 31;
    int ty = threadIdx.x >> 5;
    #pragma unroll
    for (int j = 0; j < 4; j++) {
        int k = by + ty + 8 * j;
        int c = bx + tx;
        float v;
        if (c < 1024)       v = wq[(size_t)k * 1024 + c];
        else if (c < 1280)  v = wk[(size_t)k * 256 + (c - 1024)];
        else                v = wv[(size_t)k * 256 + (c - 1280)];
        t[ty + 8 * j][tx] = v;
    }
    __syncthreads();
    #pragma unroll
    for (int j = 0; j < 4; j++) {
        int c = bx + ty + 8 * j;
        Wt[(size_t)c * DMODEL + by + tx] = __float2half_rn(t[tx][ty + 8 * j]);
    }
}

// ---------------- fp16 transpose: dst[C][R] = half(src[R][C]) ----------------
__global__ __launch_bounds__(256)
void transpose_h_kernel(const float* __restrict__ src, __half* __restrict__ dst,
                        int R, int C)
{
    __shared__ float t[32][33];
    int bx = blockIdx.x * 32;   // C base
    int by = blockIdx.y * 32;   // R base
    int tx = threadIdx.x & 31;
    int ty = threadIdx.x >> 5;
    #pragma unroll
    for (int j = 0; j < 4; j++)
        t[ty + 8 * j][tx] = src[(size_t)(by + ty + 8 * j) * C + bx + tx];
    __syncthreads();
    #pragma unroll
    for (int j = 0; j < 4; j++)
        dst[(size_t)(bx + ty + 8 * j) * R + by + tx] = __float2half_rn(t[tx][ty + 8 * j]);
}

__global__ void packbias_kernel(const float* __restrict__ bq, const float* __restrict__ bk,
                                const float* __restrict__ bv, float* __restrict__ bias)
{
    int i = blockIdx.x * 256 + threadIdx.x;
    if (i < QKVN)
        bias[i] = (i < 1024) ? bq[i] : (i < 1280 ? bk[i - 1024] : bv[i - 1280]);
}

// ---------------- RMSNorm over D=1024, fp16 output ----------------
__global__ __launch_bounds__(256)
void rmsnorm_kernel(const float* __restrict__ x, const float* __restrict__ w,
                    __half* __restrict__ y)
{
    int row = blockIdx.x;
    int i = threadIdx.x;
    const float* xr = x + (size_t)row * DMODEL;
    float4 xv = *(const float4*)(xr + i * 4);
    float ss = xv.x * xv.x + xv.y * xv.y + xv.z * xv.z + xv.w * xv.w;
    #pragma unroll
    for (int off = 16; off; off >>= 1) ss += __shfl_xor_sync(0xffffffffu, ss, off);
    __shared__ float red[8];
    __shared__ float s_sc;
    if ((i & 31) == 0) red[i >> 5] = ss;
    __syncthreads();
    if (i == 0) {
        float tot = 0.f;
        #pragma unroll
        for (int kk = 0; kk < 8; kk++) tot += red[kk];
        s_sc = rsqrtf(tot * (1.0f / DMODEL) + EPS_F);
    }
    __syncthreads();
    float sc = s_sc;
    float4 wv = *(const float4*)(w + i * 4);
    uint2 u;
    u.x = packh2(xv.x * sc * wv.x, xv.y * sc * wv.y);
    u.y = packh2(xv.z * sc * wv.z, xv.w * sc * wv.w);
    *(uint2*)(y + (size_t)row * DMODEL + i * 4) = u;
}

// ---------------- per-head QK RMSNorm + RoPE + relayout (fp16 out) ----------------
__global__ __launch_bounds__(256)
void qkrope_kernel(const float* __restrict__ qkv, const float* __restrict__ qn_w,
                   const float* __restrict__ kn_w, __half* __restrict__ Qo,
                   __half* __restrict__ Ko, __half* __restrict__ Vo)
{
    int t = blockIdx.x;            // token = s*BATCH + b
    int ty = threadIdx.y;          // 0..3
    int slot = blockIdx.y * 4 + ty;
    int i = threadIdx.x;           // 0..63
    int s = t / BATCH, b = t % BATCH;
    __shared__ float buf[4][64];
    __shared__ float red[4][2];

    if (slot >= 20) {   // V: relayout + fp16 convert (whole block is V)
        int vh = slot - 20;
        float v = qkv[(size_t)t * QKVN + 1280 + vh * 64 + i];
        Vo[((size_t)(b * NKV + vh) * S_LEN + s) * 64 + i] = __float2half_rn(v);
        return;
    }

    bool is_q = (slot < 16);
    int col = is_q ? (slot * 64 + i) : (1024 + (slot - 16) * 64 + i);
    float v = qkv[(size_t)t * QKVN + col];
    float ss = v * v;
    #pragma unroll
    for (int off = 16; off; off >>= 1) ss += __shfl_xor_sync(0xffffffffu, ss, off);
    if ((i & 31) == 0) red[ty][i >> 5] = ss;
    __syncthreads();
    float tot = red[ty][0] + red[ty][1];
    float sc = rsqrtf(tot * (1.0f / 64.0f) + EPS_F);
    const float* w = is_q ? qn_w : kn_w;
    float nv = v * sc * w[i];
    buf[ty][i] = nv;
    __syncthreads();
    float rot = (i < 32) ? -buf[ty][i + 32] : buf[ty][i - 32];
    int j = i & 31;
    float invf = exp2f(-(float)j * (13.287712379549449f / 32.0f));
    float ang = (float)s * invf;
    float sn, cs;
    sincosf(ang, &sn, &cs);
    float outv = nv * cs + rot * sn;
    if (is_q) {
        outv *= QK_SCALE;
        Qo[((size_t)(b * NHEAD + slot) * S_LEN + s) * 64 + i] = __float2half_rn(outv);
    } else {
        Ko[((size_t)(b * NKV + (slot - 16)) * S_LEN + s) * 64 + i] = __float2half_rn(outv);
    }
}

// ---------------- fp16 GEMM stage loader: 8 cp.async per thread ----------------
__device__ __forceinline__ void gf_load(uint32_t sA, uint32_t sB,
                                        const __half* Ag, const __half* Bg,
                                        int K, int k0, int tid)
{
    int r0 = tid >> 2;             // 0..31
    int ch = (tid & 3) << 3;       // half offset in row: 0,8,16,24
    #pragma unroll
    for (int j = 0; j < 4; j++) {
        int r = r0 + 32 * j;
        uint32_t so = (uint32_t)(r * 80 + ch * 2);
        cp16s(sA + so, Ag + (size_t)r * K + k0 + ch);
        cp16s(sB + so, Bg + (size_t)r * K + k0 + ch);
    }
    asm volatile("cp.async.commit_group;" ::: "memory");
}

// ---------------- fp16 GEMM (unchanged from R10) ----------------
template<int EPI>
__global__ __launch_bounds__(128)
void gemm_f16_kernel(const __half* __restrict__ A, const __half* __restrict__ Bt,
                     const float* __restrict__ bias, const float* __restrict__ res,
                     void* __restrict__ Cout, int M, int N, int K)
{
    extern __shared__ char smc[];
    uint32_t smem_base;
    asm("{ .reg .u64 t; cvta.to.shared.u64 t, %1; cvt.u32.u64 %0, t; }"
        : "=r"(smem_base) : "l"(smc));

    int tid  = threadIdx.x;
    int wid  = tid >> 5, lane = tid & 31;
    int g    = lane >> 2;
    int q    = lane & 3;
    int wm   = (wid >> 1) * 64;
    int wn   = (wid & 1) * 64;

    int row0 = blockIdx.y * 128;
    int col0 = blockIdx.x * 128;
    const __half* Ag = A  + (size_t)row0 * K;
    const __half* Bg = Bt + (size_t)col0 * K;

    float acc[4][8][4];
    #pragma unroll
    for (int mt = 0; mt < 4; mt++)
        #pragma unroll
        for (int nt = 0; nt < 8; nt++)
            #pragma unroll
            for (int r = 0; r < 4; r++) acc[mt][nt][r] = 0.f;

    const int KT = K >> 5;

    #pragma unroll
    for (int st = 0; st < 3; st++)
        gf_load(smem_base + st * GF_TILE_BYTES,
                smem_base + (GF_STAGES + st) * GF_TILE_BYTES,
                Ag, Bg, K, st * 32, tid);

    for (int kt = 0; kt < KT; kt++) {
        asm volatile("cp.async.wait_group 2;" ::: "memory");
        __syncthreads();

        if (kt + 3 < KT) {
            int st = (kt + 3) & 3;
            gf_load(smem_base + st * GF_TILE_BYTES,
                    smem_base + (GF_STAGES + st) * GF_TILE_BYTES,
                    Ag, Bg, K, (kt + 3) * 32, tid);
        }

        int st = kt & 3;
        const __half* As = (const __half*)(smc + st * GF_TILE_BYTES);
        const __half* Bs = (const __half*)(smc + (GF_STAGES + st) * GF_TILE_BYTES);

        #pragma unroll
        for (int kk = 0; kk < 32; kk += 16) {
            unsigned af[4][4];
            #pragma unroll
            for (int mt = 0; mt < 4; mt++) {
                int r = wm + mt * 16 + g;
                af[mt][0] = *(const unsigned*)(As + r * 40 + kk + 2 * q);
                af[mt][1] = *(const unsigned*)(As + (r + 8) * 40 + kk + 2 * q);
                af[mt][2] = *(const unsigned*)(As + r * 40 + kk + 2 * q + 8);
                af[mt][3] = *(const unsigned*)(As + (r + 8) * 40 + kk + 2 * q + 8);
            }
            unsigned bf[8][2];
            #pragma unroll
            for (int nt = 0; nt < 8; nt++) {
                int c = wn + nt * 8 + g;
                bf[nt][0] = *(const unsigned*)(Bs + c * 40 + kk + 2 * q);
                bf[nt][1] = *(const unsigned*)(Bs + c * 40 + kk + 2 * q + 8);
            }
            #pragma unroll
            for (int mt = 0; mt < 4; mt++)
                #pragma unroll
                for (int nt = 0; nt < 8; nt++) {
                    asm volatile(
                        "mma.sync.aligned.m16n8k16.row.col.f32.f16.f16.f32 "
                        "{%0,%1,%2,%3}, {%4,%5,%6,%7}, {%8,%9}, {%0,%1,%2,%3};"
                        : "+f"(acc[mt][nt][0]), "+f"(acc[mt][nt][1]),
                          "+f"(acc[mt][nt][2]), "+f"(acc[mt][nt][3])
                        : "r"(af[mt][0]), "r"(af[mt][1]), "r"(af[mt][2]), "r"(af[mt][3]),
                          "r"(bf[nt][0]), "r"(bf[nt][1]));
                }
        }
    }

    #pragma unroll
    for (int mt = 0; mt < 4; mt++) {
        int r = row0 + wm + mt * 16 + g;
        #pragma unroll
        for (int nt = 0; nt < 8; nt++) {
            int c = col0 + wn + nt * 8 + 2 * q;
            float bv0 = bias[c], bv1 = bias[c + 1];
            float v00 = acc[mt][nt][0] + bv0;
            float v01 = acc[mt][nt][1] + bv1;
            float v10 = acc[mt][nt][2] + bv0;
            float v11 = acc[mt][nt][3] + bv1;
            if (EPI == 1) {
                v00 = 0.5f * v00 * (1.0f + erff(v00 * 0.70710678118654752f));
                v01 = 0.5f * v01 * (1.0f + erff(v01 * 0.70710678118654752f));
                v10 = 0.5f * v10 * (1.0f + erff(v10 * 0.70710678118654752f));
                v11 = 0.5f * v11 * (1.0f + erff(v11 * 0.70710678118654752f));
                __half* C = (__half*)Cout;
                *(unsigned*)(C + (size_t)r * N + c)       = packh2(v00, v01);
                *(unsigned*)(C + (size_t)(r + 8) * N + c) = packh2(v10, v11);
            } else {
                float* C = (float*)Cout;
                if (EPI == 2) {
                    float2 r0 = *(const float2*)(res + (size_t)r * N + c);
                    float2 r1 = *(const float2*)(res + (size_t)(r + 8) * N + c);
                    v00 += r0.x; v01 += r0.y;
                    v10 += r1.x; v11 += r1.y;
                }
                *(float2*)(C + (size_t)r * N + c)       = make_float2(v00, v01);
                *(float2*)(C + (size_t)(r + 8) * N + c) = make_float2(v10, v11);
            }
        }
    }
}

// ---------------- fp16 flash attention ----------------
// BQ=64, BKV=64, 4 warps (warp w owns q-rows 16w..16w+15), causal, GQA.
// QK^T: mma.m16n8k16.f16. P*V: C-fragment of S == A-fragment of PV (half2-packed),
// V B-fragments via ldmatrix.x4.trans. Softmax in fp32. Output fp16.
__global__ __launch_bounds__(128)
void attn_f16_kernel(const __half* __restrict__ Q, const __half* __restrict__ K,
                     const __half* __restrict__ V, __half* __restrict__ O)
{
    __shared__ __half Qs[64][72];
    __shared__ __half Ks[64][72];
    __shared__ __half Vs[64][72];

    int tid  = threadIdx.x;
    int wid  = tid >> 5, lane = tid & 31;
    int g    = lane >> 2;
    int q    = lane & 3;
    int qt   = blockIdx.x;
    int bh   = blockIdx.y;
    int b    = bh >> 4;
    int h    = bh & 15;
    int kvh  = h >> 2;
    int q0   = qt * 64;

    const __half* Qb = Q + (size_t)(b * NHEAD + h)  * S_LEN * 64 + (size_t)q0 * 64;
    const __half* Kb = K + (size_t)(b * NKV  + kvh) * S_LEN * 64;
    const __half* Vb = V + (size_t)(b * NKV  + kvh) * S_LEN * 64;

    // stage Q: 64 rows x 64 halves (8x uint4 per row)
    for (int i = tid; i < 64 * 8; i += 128) {
        int r = i >> 3, c = (i & 7) * 8;
        *(uint4*)&Qs[r][c] = *(const uint4*)(Qb + (size_t)r * 64 + c);
    }

    float m0 = -INFINITY, m1 = -INFINITY, l0 = 0.f, l1 = 0.f;
    float o[8][4];
    #pragma unroll
    for (int nt = 0; nt < 8; nt++)
        #pragma unroll
        for (int r = 0; r < 4; r++) o[nt][r] = 0.f;

    int row_a = 16 * wid + g;
    int nkt = qt + 1;

    // ldmatrix lane address components (within V tile)
    int vmat = lane >> 3;          // 0..3
    int vrow = lane & 7;           // 0..7

    for (int jt = 0; jt < nkt; ++jt) {
        int j0 = jt * 64;
        __syncthreads();
        for (int i = tid; i < 64 * 8; i += 128) {
            int r = i >> 3, c = (i & 7) * 8;
            *(uint4*)&Ks[r][c] = *(const uint4*)(Kb + (size_t)(j0 + r) * 64 + c);
            *(uint4*)&Vs[r][c] = *(const uint4*)(Vb + (size_t)(j0 + r) * 64 + c);
        }
        __syncthreads();

        // ---- S = Q K^T : 4 k-chunks x 8 n-tiles ----
        float s[8][4];
        #pragma unroll
        for (int nt = 0; nt < 8; nt++)
            #pragma unroll
            for (int r = 0; r < 4; r++) s[nt][r] = 0.f;

        #pragma unroll
        for (int kk = 0; kk < 64; kk += 16) {
            unsigned a0 = *(const unsigned*)&Qs[row_a][kk + 2 * q];
            unsigned a1 = *(const unsigned*)&Qs[row_a + 8][kk + 2 * q];
            unsigned a2 = *(const unsigned*)&Qs[row_a][kk + 2 * q + 8];
            unsigned a3 = *(const unsigned*)&Qs[row_a + 8][kk + 2 * q + 8];
            #pragma unroll
            for (int nt = 0; nt < 8; nt++) {
                unsigned b0 = *(const unsigned*)&Ks[nt * 8 + g][kk + 2 * q];
                unsigned b1 = *(const unsigned*)&Ks[nt * 8 + g][kk + 2 * q + 8];
                asm volatile(
                    "mma.sync.aligned.m16n8k16.row.col.f32.f16.f16.f32 "
                    "{%0,%1,%2,%3}, {%4,%5,%6,%7}, {%8,%9}, {%0,%1,%2,%3};"
                    : "+f"(s[nt][0]), "+f"(s[nt][1]), "+f"(s[nt][2]), "+f"(s[nt][3])
                    : "r"(a0), "r"(a1), "r"(a2), "r"(a3), "r"(b0), "r"(b1));
            }
        }

        // ---- causal mask (diagonal tile only) ----
        if (jt == qt) {
            #pragma unroll
            for (int nt = 0; nt < 8; nt++) {
                int col = nt * 8 + 2 * q;
                if (col     > row_a)     s[nt][0] = -INFINITY;
                if (col + 1 > row_a)     s[nt][1] = -INFINITY;
                if (col     > row_a + 8) s[nt][2] = -INFINITY;
                if (col + 1 > row_a + 8) s[nt][3] = -INFINITY;
            }
        }

        // ---- online softmax ----
        float mt0 = -INFINITY, mt1 = -INFINITY;
        #pragma unroll
        for (int nt = 0; nt < 8; nt++) {
            mt0 = fmaxf(mt0, fmaxf(s[nt][0], s[nt][1]));
            mt1 = fmaxf(mt1, fmaxf(s[nt][2], s[nt][3]));
        }
        #pragma unroll
        for (int off = 1; off < 4; off <<= 1) {
            mt0 = fmaxf(mt0, __shfl_xor_sync(0xffffffffu, mt0, off));
            mt1 = fmaxf(mt1, __shfl_xor_sync(0xffffffffu, mt1, off));
        }
        float mn0 = fmaxf(m0, mt0), mn1 = fmaxf(m1, mt1);
        float al0 = __expf(m0 - mn0), al1 = __expf(m1 - mn1);
        m0 = mn0; m1 = mn1;
        float ps0 = 0.f, ps1 = 0.f;
        #pragma unroll
        for (int nt = 0; nt < 8; nt++) {
            s[nt][0] = __expf(s[nt][0] - mn0);
            s[nt][1] = __expf(s[nt][1] - mn0);
            s[nt][2] = __expf(s[nt][2] - mn1);
            s[nt][3] = __expf(s[nt][3] - mn1);
            ps0 += s[nt][0] + s[nt][1];
            ps1 += s[nt][2] + s[nt][3];
            o[nt][0] *= al0; o[nt][1] *= al0;
            o[nt][2] *= al1; o[nt][3] *= al1;
        }
        #pragma unroll
        for (int off = 1; off < 4; off <<= 1) {
            ps0 += __shfl_xor_sync(0xffffffffu, ps0, off);
            ps1 += __shfl_xor_sync(0xffffffffu, ps1, off);
        }
        l0 = l0 * al0 + ps0;
        l1 = l1 * al1 + ps1;

        // ---- O += P V : C-frag of S -> A-frag directly; V via ldmatrix.trans ----
        #pragma unroll
        for (int kc = 0; kc < 4; kc++) {
            unsigned a0 = packh2(s[2 * kc][0],     s[2 * kc][1]);
            unsigned a1 = packh2(s[2 * kc][2],     s[2 * kc][3]);
            unsigned a2 = packh2(s[2 * kc + 1][0], s[2 * kc + 1][1]);
            unsigned a3 = packh2(s[2 * kc + 1][2], s[2 * kc + 1][3]);
            #pragma unroll
            for (int ntp = 0; ntp < 4; ntp++) {
                const __half* vp = &Vs[kc * 16 + (vmat & 1) * 8 + vrow]
                                      [ntp * 16 + (vmat >> 1) * 8];
                uint32_t vaddr = (uint32_t)__cvta_generic_to_shared(vp);
                unsigned v0, v1, v2, v3;
                asm volatile(
                    "ldmatrix.sync.aligned.m8n8.x4.trans.shared.b16 {%0,%1,%2,%3}, [%4];"
                    : "=r"(v0), "=r"(v1), "=r"(v2), "=r"(v3) : "r"(vaddr));
                asm volatile(
                    "mma.sync.aligned.m16n8k16.row.col.f32.f16.f16.f32 "
                    "{%0,%1,%2,%3}, {%4,%5,%6,%7}, {%8,%9}, {%0,%1,%2,%3};"
                    : "+f"(o[2 * ntp][0]), "+f"(o[2 * ntp][1]),
                      "+f"(o[2 * ntp][2]), "+f"(o[2 * ntp][3])
                    : "r"(a0), "r"(a1), "r"(a2), "r"(a3), "r"(v0), "r"(v1));
                asm volatile(
                    "mma.sync.aligned.m16n8k16.row.col.f32.f16.f16.f32 "
                    "{%0,%1,%2,%3}, {%4,%5,%6,%7}, {%8,%9}, {%0,%1,%2,%3};"
                    : "+f"(o[2 * ntp + 1][0]), "+f"(o[2 * ntp + 1][1]),
                      "+f"(o[2 * ntp + 1][2]), "+f"(o[2 * ntp + 1][3])
                    : "r"(a0), "r"(a1), "r"(a2), "r"(a3), "r"(v2), "r"(v3));
            }
        }
    }

    // ---- epilogue: normalize, write fp16 [token, D] ----
    float inv0 = 1.0f / l0, inv1 = 1.0f / l1;
    int srow0 = q0 + row_a;
    int srow1 = srow0 + 8;
    #pragma unroll
    for (int nt = 0; nt < 8; nt++) {
        int c = h * 64 + nt * 8 + 2 * q;
        *(unsigned*)(O + ((size_t)srow0 * BATCH + b) * DMODEL + c) =
            packh2(o[nt][0] * inv0, o[nt][1] * inv0);
        *(unsigned*)(O + ((size_t)srow1 * BATCH + b) * DMODEL + c) =
            packh2(o[nt][2] * inv1, o[nt][3] * inv1);
    }
}

// ---------------- host orchestration ----------------
extern "C" void kernel_launch(void* const* d_in, const int* in_sizes, int n_in,
                              void* d_out, int out_size)
{
    const float* x   = (const float*)d_in[0];
    const float* n1w = (const float*)d_in[1];
    const float* wq  = (const float*)d_in[2];
    const float* bq  = (const float*)d_in[3];
    const float* wk  = (const float*)d_in[4];
    const float* bk  = (const float*)d_in[5];
    const float* wv  = (const float*)d_in[6];
    const float* bv  = (const float*)d_in[7];
    const float* qnw = (const float*)d_in[8];
    const float* knw = (const float*)d_in[9];
    const float* wo  = (const float*)d_in[10];
    const float* bo  = (const float*)d_in[11];
    const float* n2w = (const float*)d_in[12];
    const float* w1  = (const float*)d_in[13];
    const float* b1  = (const float*)d_in[14];
    const float* w2  = (const float*)d_in[15];
    const float* b2  = (const float*)d_in[16];

    __half *ph, *pwqkv, *pattn, *ph2, *pmid, *pwor, *pw1r, *pw2r, *pq, *pk, *pv;
    float *pbqkv, *pqkv, *px1;
    cudaGetSymbolAddress((void**)&ph,    g_h);
    cudaGetSymbolAddress((void**)&pwqkv, g_wqkv);
    cudaGetSymbolAddress((void**)&pbqkv, g_bqkv);
    cudaGetSymbolAddress((void**)&pqkv,  g_qkv);
    cudaGetSymbolAddress((void**)&pq,    g_q);
    cudaGetSymbolAddress((void**)&pk,    g_k);
    cudaGetSymbolAddress((void**)&pv,    g_v);
    cudaGetSymbolAddress((void**)&pattn, g_attn);
    cudaGetSymbolAddress((void**)&px1,   g_x1);
    cudaGetSymbolAddress((void**)&ph2,   g_h2);
    cudaGetSymbolAddress((void**)&pmid,  g_mid);
    cudaGetSymbolAddress((void**)&pwor,  g_wor);
    cudaGetSymbolAddress((void**)&pw1r,  g_w1r);
    cudaGetSymbolAddress((void**)&pw2r,  g_w2r);

    cudaFuncSetAttribute(gemm_f16_kernel<0>,
                         cudaFuncAttributeMaxDynamicSharedMemorySize, GF_SMEM_BYTES);
    cudaFuncSetAttribute(gemm_f16_kernel<1>,
                         cudaFuncAttributeMaxDynamicSharedMemorySize, GF_SMEM_BYTES);
    cudaFuncSetAttribute(gemm_f16_kernel<2>,
                         cudaFuncAttributeMaxDynamicSharedMemorySize, GF_SMEM_BYTES);

    // weight prep (fp16 transposes to [N,K])
    pack_wqkv_t_kernel<<<dim3(QKVN / 32, DMODEL / 32), 256>>>(wq, wk, wv, pwqkv);
    packbias_kernel<<<6, 256>>>(bq, bk, bv, pbqkv);
    transpose_h_kernel<<<dim3(DMODEL / 32, DMODEL / 32), 256>>>(wo, pwor, DMODEL, DMODEL);
    transpose_h_kernel<<<dim3(DFF / 32, DMODEL / 32), 256>>>(w1, pw1r, DMODEL, DFF);
    transpose_h_kernel<<<dim3(DMODEL / 32, DFF / 32), 256>>>(w2, pw2r, DFF, DMODEL);

    rmsnorm_kernel<<<NTOK, 256>>>(x, n1w, ph);
    gemm_f16_kernel<0><<<dim3(QKVN / 128, NTOK / 128), 128, GF_SMEM_BYTES>>>(
        ph, pwqkv, pbqkv, nullptr, pqkv, NTOK, QKVN, DMODEL);
    qkrope_kernel<<<dim3(NTOK, 6), dim3(64, 4)>>>(pqkv, qnw, knw, pq, pk, pv);
    attn_f16_kernel<<<dim3(S_LEN / 64, BATCH * NHEAD), 128>>>(pq, pk, pv, pattn);
    gemm_f16_kernel<2><<<dim3(DMODEL / 128, NTOK / 128), 128, GF_SMEM_BYTES>>>(
        pattn, pwor, bo, x, px1, NTOK, DMODEL, DMODEL);
    rmsnorm_kernel<<<NTOK, 256>>>(px1, n2w, ph2);
    gemm_f16_kernel<1><<<dim3(DFF / 128, NTOK / 128), 128, GF_SMEM_BYTES>>>(
        ph2, pw1r, b1, nullptr, pmid, NTOK, DFF, DMODEL);
    gemm_f16_kernel<2><<<dim3(DMODEL / 128, NTOK / 128), 128, GF_SMEM_BYTES>>>(
        pmid, pw2r, b2, px1, d_out, NTOK, DMODEL, DFF);
}